// round 1
// baseline (speedup 1.0000x reference)
#include <cuda_runtime.h>
#include <math.h>

// ---------------------------------------------------------------------------
// Problem constants
// ---------------------------------------------------------------------------
#define NTOK   16384          // B*L = 4*4096
#define DMOD   1152           // D
#define D3C    384            // D/3
#define NHEAD  16
#define DK3C   24             // per-head dim within a group
#define ROWS3  (NTOK * 3)     // 49152  rows of the projection GEMMs

// 1/sqrt(72)
#define SCORE_SCALE 0.1178511301977579f

// ---------------------------------------------------------------------------
// Scratch (static device globals -- allocation is forbidden in kernel_launch)
// ---------------------------------------------------------------------------
__device__ float g_xn[NTOK * DMOD];          // layernormed x  (= [ROWS3, 384] view)
__device__ float g_proj[4][ROWS3 * D3C];     // q, k, v, gate  (each [ROWS3, 384])
__device__ float g_hout[NTOK * DMOD];        // attention output back in [N, D] layout

// ---------------------------------------------------------------------------
// Kernel 1: LayerNorm over D=1152.  One block per token, 288 threads,
// each thread owns one float4 (288*4 = 1152).
// ---------------------------------------------------------------------------
__global__ void ln_kernel(const float* __restrict__ x,
                          const float* __restrict__ gamma,
                          const float* __restrict__ beta,
                          float* __restrict__ xn) {
    const int n = blockIdx.x;
    const int t = threadIdx.x;                 // 0..287
    const float4* xr = reinterpret_cast<const float4*>(x + (size_t)n * DMOD);
    float4 v = xr[t];

    float s  = v.x + v.y + v.z + v.w;
    float ss = v.x * v.x + v.y * v.y + v.z * v.z + v.w * v.w;

    // warp reduce
    #pragma unroll
    for (int off = 16; off > 0; off >>= 1) {
        s  += __shfl_xor_sync(0xffffffffu, s,  off);
        ss += __shfl_xor_sync(0xffffffffu, ss, off);
    }
    __shared__ float red_s[9], red_ss[9], stat[2];
    const int warp = t >> 5, lane = t & 31;
    if (lane == 0) { red_s[warp] = s; red_ss[warp] = ss; }
    __syncthreads();
    if (t == 0) {
        float ts = 0.f, tss = 0.f;
        #pragma unroll
        for (int i = 0; i < 9; i++) { ts += red_s[i]; tss += red_ss[i]; }
        float mu  = ts * (1.0f / DMOD);
        float var = tss * (1.0f / DMOD) - mu * mu;
        stat[0] = mu;
        stat[1] = rsqrtf(var + 1e-6f);
    }
    __syncthreads();
    const float mu = stat[0], rstd = stat[1];

    const float4 gm = reinterpret_cast<const float4*>(gamma)[t];
    const float4 be = reinterpret_cast<const float4*>(beta)[t];
    float4 o;
    o.x = (v.x - mu) * rstd * gm.x + be.x;
    o.y = (v.y - mu) * rstd * gm.y + be.y;
    o.z = (v.z - mu) * rstd * gm.z + be.z;
    o.w = (v.w - mu) * rstd * gm.w + be.w;
    reinterpret_cast<float4*>(xn + (size_t)n * DMOD)[t] = o;
}

// ---------------------------------------------------------------------------
// Kernel 2: SGEMM  C[M,N] = A[M,K] @ W[N,K]^T + bias  (+ optional resid*g)
// Both A and W are K-contiguous.  128x128x8 tile, 256 threads, 8x8 per thread.
// Requires M%128==0, N%128==0, K%8==0 (holds for all our shapes).
// ---------------------------------------------------------------------------
__global__ __launch_bounds__(256, 2)
void sgemm_nt(const float* __restrict__ A, const float* __restrict__ W,
              const float* __restrict__ bias, float* __restrict__ C,
              const float* __restrict__ resid, const float* __restrict__ gptr,
              int M, int N, int K) {
    __shared__ float As[8][128];
    __shared__ float Bs[8][128];

    const int tid = threadIdx.x;
    const int bm = blockIdx.y * 128;
    const int bn = blockIdx.x * 128;

    const int lrow  = tid >> 1;         // 0..127 : tile row being loaded
    const int lcol4 = (tid & 1) * 4;    // 0 or 4 : k offset within the 8-wide slab

    const int tx = tid & 15;            // n-dir thread coord
    const int ty = tid >> 4;            // m-dir thread coord

    float acc[8][8];
    #pragma unroll
    for (int i = 0; i < 8; i++)
        #pragma unroll
        for (int j = 0; j < 8; j++) acc[i][j] = 0.f;

    const float* Arow = A + (size_t)(bm + lrow) * K + lcol4;
    const float* Wrow = W + (size_t)(bn + lrow) * K + lcol4;

    for (int k0 = 0; k0 < K; k0 += 8) {
        const float4 av = *reinterpret_cast<const float4*>(Arow + k0);
        const float4 bv = *reinterpret_cast<const float4*>(Wrow + k0);
        __syncthreads();
        As[lcol4 + 0][lrow] = av.x;  As[lcol4 + 1][lrow] = av.y;
        As[lcol4 + 2][lrow] = av.z;  As[lcol4 + 3][lrow] = av.w;
        Bs[lcol4 + 0][lrow] = bv.x;  Bs[lcol4 + 1][lrow] = bv.y;
        Bs[lcol4 + 2][lrow] = bv.z;  Bs[lcol4 + 3][lrow] = bv.w;
        __syncthreads();

        #pragma unroll
        for (int kk = 0; kk < 8; kk++) {
            float4 a0 = *reinterpret_cast<const float4*>(&As[kk][ty * 8]);
            float4 a1 = *reinterpret_cast<const float4*>(&As[kk][ty * 8 + 4]);
            float4 b0 = *reinterpret_cast<const float4*>(&Bs[kk][tx * 8]);
            float4 b1 = *reinterpret_cast<const float4*>(&Bs[kk][tx * 8 + 4]);
            float ar[8] = {a0.x, a0.y, a0.z, a0.w, a1.x, a1.y, a1.z, a1.w};
            float br[8] = {b0.x, b0.y, b0.z, b0.w, b1.x, b1.y, b1.z, b1.w};
            #pragma unroll
            for (int i = 0; i < 8; i++)
                #pragma unroll
                for (int j = 0; j < 8; j++)
                    acc[i][j] = fmaf(ar[i], br[j], acc[i][j]);
        }
    }

    const float gval = (gptr != nullptr) ? *gptr : 0.f;
    const int coln = bn + tx * 8;
    #pragma unroll
    for (int i = 0; i < 8; i++) {
        const int row = bm + ty * 8 + i;
        float* crow = C + (size_t)row * N + coln;
        const float* rrow = (resid != nullptr) ? (resid + (size_t)row * N + coln) : nullptr;
        float out[8];
        #pragma unroll
        for (int j = 0; j < 8; j++) {
            float v = acc[i][j] + bias[coln + j];
            if (rrow) v = fmaf(rrow[j], gval, v);
            out[j] = v;
        }
        *reinterpret_cast<float4*>(crow)     = make_float4(out[0], out[1], out[2], out[3]);
        *reinterpret_cast<float4*>(crow + 4) = make_float4(out[4], out[5], out[6], out[7]);
    }
}

// ---------------------------------------------------------------------------
// Kernel 3: per-(token, head) 3x3 attention + sigmoid gate.
// One warp per (n, h); lanes 0..23 carry the dk3 dimension.
// q/k/v/gate live at g_proj[p][(n*3+i)*384 + h*24 + d].
// Output written to g_hout[n*1152 + i*384 + h*24 + d].
// ---------------------------------------------------------------------------
__global__ void attn_kernel() {
    const int gwarp = (blockIdx.x * blockDim.x + threadIdx.x) >> 5;
    const int lane  = threadIdx.x & 31;
    const int n = gwarp / NHEAD;
    const int h = gwarp % NHEAD;
    const bool act = lane < DK3C;
    const int d = act ? lane : 0;

    const int off = h * DK3C + d;
    float q[3], k[3], v[3], gt[3];
    #pragma unroll
    for (int i = 0; i < 3; i++) {
        const size_t idx = (size_t)(n * 3 + i) * D3C + off;
        q[i]  = act ? g_proj[0][idx] : 0.f;
        k[i]  = act ? g_proj[1][idx] : 0.f;
        v[i]  = act ? g_proj[2][idx] : 0.f;
        gt[i] = act ? g_proj[3][idx] : 0.f;
    }

    float s[3][3];
    #pragma unroll
    for (int i = 0; i < 3; i++)
        #pragma unroll
        for (int j = 0; j < 3; j++) {
            float p = q[i] * k[j];
            #pragma unroll
            for (int offm = 16; offm > 0; offm >>= 1)
                p += __shfl_xor_sync(0xffffffffu, p, offm);
            s[i][j] = p * SCORE_SCALE;
        }

    #pragma unroll
    for (int i = 0; i < 3; i++) {
        float m = fmaxf(s[i][0], fmaxf(s[i][1], s[i][2]));
        float e0 = expf(s[i][0] - m), e1 = expf(s[i][1] - m), e2 = expf(s[i][2] - m);
        float inv = 1.0f / (e0 + e1 + e2);
        float o = (e0 * v[0] + e1 * v[1] + e2 * v[2]) * inv;
        o *= 1.0f / (1.0f + expf(-gt[i]));
        if (act)
            g_hout[(size_t)n * DMOD + i * D3C + off] = o;
    }
}

// ---------------------------------------------------------------------------
// Launch
// ---------------------------------------------------------------------------
extern "C" void kernel_launch(void* const* d_in, const int* in_sizes, int n_in,
                              void* d_out, int out_size) {
    const float* x     = (const float*)d_in[0];
    const float* ln_g  = (const float*)d_in[1];
    const float* ln_b  = (const float*)d_in[2];
    const float* Wq    = (const float*)d_in[3];
    const float* bq    = (const float*)d_in[4];
    const float* Wk    = (const float*)d_in[5];
    const float* bk    = (const float*)d_in[6];
    const float* Wv    = (const float*)d_in[7];
    const float* bv    = (const float*)d_in[8];
    const float* Wg    = (const float*)d_in[9];
    const float* bg    = (const float*)d_in[10];
    const float* Wo    = (const float*)d_in[11];
    const float* bo    = (const float*)d_in[12];
    const float* gsc   = (const float*)d_in[13];
    float* out = (float*)d_out;

    float *p_xn, *p_proj, *p_hout;
    cudaGetSymbolAddress((void**)&p_xn,   g_xn);
    cudaGetSymbolAddress((void**)&p_proj, g_proj);
    cudaGetSymbolAddress((void**)&p_hout, g_hout);
    float* p_q = p_proj;
    float* p_k = p_proj + (size_t)1 * ROWS3 * D3C;
    float* p_v = p_proj + (size_t)2 * ROWS3 * D3C;
    float* p_g = p_proj + (size_t)3 * ROWS3 * D3C;

    // 1) LayerNorm
    ln_kernel<<<NTOK, 288>>>(x, ln_g, ln_b, p_xn);

    // 2) Four projection GEMMs: [49152,384] @ [384,384]^T
    {
        dim3 grid(D3C / 128, ROWS3 / 128);   // (3, 384)
        sgemm_nt<<<grid, 256>>>(p_xn, Wq, bq, p_q, nullptr, nullptr, ROWS3, D3C, D3C);
        sgemm_nt<<<grid, 256>>>(p_xn, Wk, bk, p_k, nullptr, nullptr, ROWS3, D3C, D3C);
        sgemm_nt<<<grid, 256>>>(p_xn, Wv, bv, p_v, nullptr, nullptr, ROWS3, D3C, D3C);
        sgemm_nt<<<grid, 256>>>(p_xn, Wg, bg, p_g, nullptr, nullptr, ROWS3, D3C, D3C);
    }

    // 3) Attention + gate  (one warp per (token, head))
    {
        const int warps = NTOK * NHEAD;          // 262144
        attn_kernel<<<warps * 32 / 256, 256>>>();
    }

    // 4) Output GEMM + bias + residual*g : [16384,1152] @ [1152,1152]^T
    {
        dim3 grid(DMOD / 128, NTOK / 128);       // (9, 128)
        sgemm_nt<<<grid, 256>>>(p_hout, Wo, bo, out, x, gsc, NTOK, DMOD, DMOD);
    }
}

// round 3
// speedup vs baseline: 1.9124x; 1.9124x over previous
#include <cuda_runtime.h>
#include <cstdint>
#include <math.h>

// ---------------------------------------------------------------------------
// Problem constants
// ---------------------------------------------------------------------------
#define NTOK   16384          // B*L
#define DMOD   1152           // D
#define D3C    384            // D/3
#define NHEAD  16
#define DK3C   24
#define ROWS3  (NTOK * 3)     // 49152
#define SCORE_SCALE 0.1178511301977579f   // 1/sqrt(72)

#define W4SZ   (D3C * D3C)            // 147456
#define WOSZ   (DMOD * DMOD)          // 1327104
#define WO_OFF (4 * W4SZ)             // 589824

// ---------------------------------------------------------------------------
// Scratch
// ---------------------------------------------------------------------------
__device__ float g_xn[NTOK * DMOD];           // tf32-rounded LN output
__device__ float g_proj[4][ROWS3 * D3C];      // q,k,v,gate (fp32)
__device__ float g_hout[NTOK * DMOD];         // tf32-rounded attention output
__device__ float g_wt[WO_OFF + WOSZ];         // tf32-rounded weights

// ---------------------------------------------------------------------------
// Helpers
// ---------------------------------------------------------------------------
__device__ __forceinline__ uint32_t f2tf32(float f) {
    uint32_t u;
    asm("cvt.rna.tf32.f32 %0, %1;" : "=r"(u) : "f"(f));
    return u;
}
__device__ __forceinline__ uint32_t smem_u32(const void* p) {
    uint32_t a;
    asm("{ .reg .u64 t; cvta.to.shared.u64 t, %1; cvt.u32.u64 %0, t; }" : "=r"(a) : "l"(p));
    return a;
}
__device__ __forceinline__ void cp_async16(uint32_t dst, const void* src) {
    asm volatile("cp.async.cg.shared.global [%0], [%1], 16;" :: "r"(dst), "l"(src));
}
__device__ __forceinline__ void cp_commit() {
    asm volatile("cp.async.commit_group;" ::: "memory");
}
template<int N>
__device__ __forceinline__ void cp_wait() {
    asm volatile("cp.async.wait_group %0;" :: "n"(N) : "memory");
}
__device__ __forceinline__ void mma_tf32(float* d, const uint32_t* a, const uint32_t* b) {
    asm volatile(
        "mma.sync.aligned.m16n8k8.row.col.f32.tf32.tf32.f32 "
        "{%0,%1,%2,%3}, {%4,%5,%6,%7}, {%8,%9}, {%0,%1,%2,%3};"
        : "+f"(d[0]), "+f"(d[1]), "+f"(d[2]), "+f"(d[3])
        : "r"(a[0]), "r"(a[1]), "r"(a[2]), "r"(a[3]), "r"(b[0]), "r"(b[1]));
}

// ---------------------------------------------------------------------------
// Kernel 1: LayerNorm (output rounded to tf32)
// ---------------------------------------------------------------------------
__global__ void ln_kernel(const float* __restrict__ x,
                          const float* __restrict__ gamma,
                          const float* __restrict__ beta,
                          float* __restrict__ xn) {
    const int n = blockIdx.x;
    const int t = threadIdx.x;
    const float4* xr = reinterpret_cast<const float4*>(x + (size_t)n * DMOD);
    float4 v = xr[t];
    float s  = v.x + v.y + v.z + v.w;
    float ss = v.x * v.x + v.y * v.y + v.z * v.z + v.w * v.w;
    #pragma unroll
    for (int off = 16; off > 0; off >>= 1) {
        s  += __shfl_xor_sync(0xffffffffu, s,  off);
        ss += __shfl_xor_sync(0xffffffffu, ss, off);
    }
    __shared__ float red_s[9], red_ss[9], stat[2];
    const int warp = t >> 5, lane = t & 31;
    if (lane == 0) { red_s[warp] = s; red_ss[warp] = ss; }
    __syncthreads();
    if (t == 0) {
        float ts = 0.f, tss = 0.f;
        #pragma unroll
        for (int i = 0; i < 9; i++) { ts += red_s[i]; tss += red_ss[i]; }
        float mu  = ts * (1.0f / DMOD);
        float var = tss * (1.0f / DMOD) - mu * mu;
        stat[0] = mu; stat[1] = rsqrtf(var + 1e-6f);
    }
    __syncthreads();
    const float mu = stat[0], rstd = stat[1];
    const float4 gm = reinterpret_cast<const float4*>(gamma)[t];
    const float4 be = reinterpret_cast<const float4*>(beta)[t];
    float4 o;
    o.x = __uint_as_float(f2tf32((v.x - mu) * rstd * gm.x + be.x));
    o.y = __uint_as_float(f2tf32((v.y - mu) * rstd * gm.y + be.y));
    o.z = __uint_as_float(f2tf32((v.z - mu) * rstd * gm.z + be.z));
    o.w = __uint_as_float(f2tf32((v.w - mu) * rstd * gm.w + be.w));
    reinterpret_cast<float4*>(xn + (size_t)n * DMOD)[t] = o;
}

// ---------------------------------------------------------------------------
// Kernel 1b: round weights to tf32 into g_wt
// ---------------------------------------------------------------------------
__global__ void prep_w(const float* __restrict__ Wq, const float* __restrict__ Wk,
                       const float* __restrict__ Wv, const float* __restrict__ Wg,
                       const float* __restrict__ Wo) {
    const int total = WO_OFF + WOSZ;
    for (int i = blockIdx.x * blockDim.x + threadIdx.x; i < total; i += gridDim.x * blockDim.x) {
        float v;
        if (i < WO_OFF) {
            const int z = i / W4SZ, r = i % W4SZ;
            const float* W = (z == 0) ? Wq : (z == 1) ? Wk : (z == 2) ? Wv : Wg;
            v = W[r];
        } else {
            v = Wo[i - WO_OFF];
        }
        g_wt[i] = __uint_as_float(f2tf32(v));
    }
}

// ---------------------------------------------------------------------------
// tf32 mma.sync GEMM: C[M,Ntot] = A[M,KD] @ W[Ntot,KD]^T + bias (+resid*g)
// 128x128x16 tiles, 128 threads, 4 warps (2x2), warp tile 64x64.
// ---------------------------------------------------------------------------
struct GemmPtrs {
    const float* bias[4];
    float*       C[4];
    const float* W[4];
    const float* resid;
    const float* g;
};

#define PITCH 20   // floats per smem row (16 data + 4 pad) -> conflict-free

template<int KD, bool RES>
__global__ __launch_bounds__(128)
void mma_gemm(const float* __restrict__ A, GemmPtrs gp, int Ntot) {
    constexpr int NC = KD / 16;
    __shared__ float smA[2][128 * PITCH];
    __shared__ float smB[2][128 * PITCH];

    const int tid  = threadIdx.x;
    const int wid  = tid >> 5;
    const int lane = tid & 31;
    const int g    = lane >> 2;     // groupID
    const int t4   = lane & 3;      // threadID_in_group
    const int wm0  = (wid >> 1) * 64;
    const int wn0  = (wid & 1) * 64;
    const int z    = blockIdx.z;

    const float* W    = gp.W[z];
    const float* bias = gp.bias[z];
    float*       C    = gp.C[z];
    const int bm = blockIdx.y * 128;
    const int bn = blockIdx.x * 128;

    const uint32_t sA0 = smem_u32(&smA[0][0]);
    const uint32_t sB0 = smem_u32(&smB[0][0]);

    // async load of one k-chunk into stage s
    const float* Asrc = A + (size_t)(bm + tid) * KD;
    const float* Wsrc = W + (size_t)(bn + tid) * KD;

    auto load_stage = [&](int s, int c) {
        const int k0 = c * 16;
        const uint32_t da = sA0 + (s * 128 * PITCH + tid * PITCH) * 4;
        const uint32_t db = sB0 + (s * 128 * PITCH + tid * PITCH) * 4;
        #pragma unroll
        for (int j = 0; j < 4; j++) {
            cp_async16(da + j * 16, Asrc + k0 + j * 4);
            cp_async16(db + j * 16, Wsrc + k0 + j * 4);
        }
        cp_commit();
    };

    float acc[4][8][4];
    #pragma unroll
    for (int i = 0; i < 4; i++)
        #pragma unroll
        for (int j = 0; j < 8; j++)
            #pragma unroll
            for (int r = 0; r < 4; r++) acc[i][j][r] = 0.f;

    load_stage(0, 0);
    load_stage(1, 1);

    for (int c = 0; c < NC; c++) {
        if (c == NC - 1) cp_wait<0>(); else cp_wait<1>();
        __syncthreads();
        const int s = c & 1;
        const float* As = &smA[s][0];
        const float* Bs = &smB[s][0];

        #pragma unroll
        for (int kk = 0; kk < 2; kk++) {
            const int kb = kk * 8;
            uint32_t afr[4][4];
            #pragma unroll
            for (int ms = 0; ms < 4; ms++) {
                const int r = wm0 + ms * 16 + g;
                afr[ms][0] = __float_as_uint(As[(r    ) * PITCH + kb + t4    ]);
                afr[ms][1] = __float_as_uint(As[(r + 8) * PITCH + kb + t4    ]);
                afr[ms][2] = __float_as_uint(As[(r    ) * PITCH + kb + t4 + 4]);
                afr[ms][3] = __float_as_uint(As[(r + 8) * PITCH + kb + t4 + 4]);
            }
            #pragma unroll
            for (int ns = 0; ns < 8; ns++) {
                const int n = wn0 + ns * 8 + g;
                uint32_t bfr[2];
                bfr[0] = __float_as_uint(Bs[n * PITCH + kb + t4    ]);
                bfr[1] = __float_as_uint(Bs[n * PITCH + kb + t4 + 4]);
                #pragma unroll
                for (int ms = 0; ms < 4; ms++)
                    mma_tf32(acc[ms][ns], afr[ms], bfr);
            }
        }
        __syncthreads();
        if (c + 2 < NC) load_stage(s, c + 2);
    }

    // Epilogue
    const float gval = RES ? __ldg(gp.g) : 0.f;
    #pragma unroll
    for (int ms = 0; ms < 4; ms++) {
        const int row0 = bm + wm0 + ms * 16 + g;
        #pragma unroll
        for (int ns = 0; ns < 8; ns++) {
            const int col = bn + wn0 + ns * 8 + 2 * t4;
            const float b0 = __ldg(bias + col);
            const float b1 = __ldg(bias + col + 1);
            float o0 = acc[ms][ns][0] + b0;
            float o1 = acc[ms][ns][1] + b1;
            float o2 = acc[ms][ns][2] + b0;
            float o3 = acc[ms][ns][3] + b1;
            if (RES) {
                const float* r0 = gp.resid + (size_t)row0 * Ntot + col;
                const float* r1 = gp.resid + (size_t)(row0 + 8) * Ntot + col;
                o0 = fmaf(r0[0], gval, o0);
                o1 = fmaf(r0[1], gval, o1);
                o2 = fmaf(r1[0], gval, o2);
                o3 = fmaf(r1[1], gval, o3);
            }
            *reinterpret_cast<float2*>(C + (size_t)row0 * Ntot + col)       = make_float2(o0, o1);
            *reinterpret_cast<float2*>(C + (size_t)(row0 + 8) * Ntot + col) = make_float2(o2, o3);
        }
    }
}

// ---------------------------------------------------------------------------
// Attention + gate (output rounded to tf32 for GEMM2)
// ---------------------------------------------------------------------------
__global__ void attn_kernel() {
    const int gwarp = (blockIdx.x * blockDim.x + threadIdx.x) >> 5;
    const int lane  = threadIdx.x & 31;
    const int n = gwarp / NHEAD;
    const int h = gwarp % NHEAD;
    const bool act = lane < DK3C;
    const int d = act ? lane : 0;
    const int off = h * DK3C + d;

    float q[3], k[3], v[3], gt[3];
    #pragma unroll
    for (int i = 0; i < 3; i++) {
        const size_t idx = (size_t)(n * 3 + i) * D3C + off;
        q[i]  = act ? g_proj[0][idx] : 0.f;
        k[i]  = act ? g_proj[1][idx] : 0.f;
        v[i]  = act ? g_proj[2][idx] : 0.f;
        gt[i] = act ? g_proj[3][idx] : 0.f;
    }
    float s[3][3];
    #pragma unroll
    for (int i = 0; i < 3; i++)
        #pragma unroll
        for (int j = 0; j < 3; j++) {
            float p = q[i] * k[j];
            #pragma unroll
            for (int om = 16; om > 0; om >>= 1)
                p += __shfl_xor_sync(0xffffffffu, p, om);
            s[i][j] = p * SCORE_SCALE;
        }
    #pragma unroll
    for (int i = 0; i < 3; i++) {
        float m = fmaxf(s[i][0], fmaxf(s[i][1], s[i][2]));
        float e0 = expf(s[i][0] - m), e1 = expf(s[i][1] - m), e2 = expf(s[i][2] - m);
        float inv = 1.0f / (e0 + e1 + e2);
        float o = (e0 * v[0] + e1 * v[1] + e2 * v[2]) * inv;
        o *= 1.0f / (1.0f + expf(-gt[i]));
        if (act)
            g_hout[(size_t)n * DMOD + i * D3C + off] = __uint_as_float(f2tf32(o));
    }
}

// ---------------------------------------------------------------------------
// Launch
// ---------------------------------------------------------------------------
extern "C" void kernel_launch(void* const* d_in, const int* in_sizes, int n_in,
                              void* d_out, int out_size) {
    const float* x    = (const float*)d_in[0];
    const float* ln_g = (const float*)d_in[1];
    const float* ln_b = (const float*)d_in[2];
    const float* Wq   = (const float*)d_in[3];
    const float* bq   = (const float*)d_in[4];
    const float* Wk   = (const float*)d_in[5];
    const float* bk   = (const float*)d_in[6];
    const float* Wv   = (const float*)d_in[7];
    const float* bv   = (const float*)d_in[8];
    const float* Wg   = (const float*)d_in[9];
    const float* bg   = (const float*)d_in[10];
    const float* Wo   = (const float*)d_in[11];
    const float* bo   = (const float*)d_in[12];
    const float* gsc  = (const float*)d_in[13];
    float* out = (float*)d_out;

    float *p_xn, *p_proj, *p_hout, *p_wt;
    cudaGetSymbolAddress((void**)&p_xn,   g_xn);
    cudaGetSymbolAddress((void**)&p_proj, g_proj);
    cudaGetSymbolAddress((void**)&p_hout, g_hout);
    cudaGetSymbolAddress((void**)&p_wt,   g_wt);

    // 1) LayerNorm + weight prep
    ln_kernel<<<NTOK, 288>>>(x, ln_g, ln_b, p_xn);
    prep_w<<<296, 256>>>(Wq, Wk, Wv, Wg, Wo);

    // 2) Four projection GEMMs (grid.z): [49152,384] @ [384,384]^T
    {
        GemmPtrs gp;
        gp.bias[0] = bq; gp.bias[1] = bk; gp.bias[2] = bv; gp.bias[3] = bg;
        for (int z = 0; z < 4; z++) {
            gp.C[z] = p_proj + (size_t)z * ROWS3 * D3C;
            gp.W[z] = p_wt + (size_t)z * W4SZ;
        }
        gp.resid = nullptr; gp.g = nullptr;
        dim3 grid(D3C / 128, ROWS3 / 128, 4);
        mma_gemm<D3C, false><<<grid, 128>>>(p_xn, gp, D3C);
    }

    // 3) Attention + gate
    attn_kernel<<<NTOK * NHEAD * 32 / 256, 256>>>();

    // 4) Output GEMM + bias + residual*g : [16384,1152] @ [1152,1152]^T
    {
        GemmPtrs gp;
        gp.bias[0] = bo; gp.C[0] = out; gp.W[0] = p_wt + WO_OFF;
        gp.bias[1] = gp.bias[2] = gp.bias[3] = nullptr;
        gp.C[1] = gp.C[2] = gp.C[3] = nullptr;
        gp.W[1] = gp.W[2] = gp.W[3] = nullptr;
        gp.resid = x; gp.g = gsc;
        dim3 grid(DMOD / 128, NTOK / 128, 1);
        mma_gemm<DMOD, true><<<grid, 128>>>(p_hout, gp, DMOD);
    }
}

// round 4
// speedup vs baseline: 2.5466x; 1.3316x over previous
#include <cuda_runtime.h>
#include <cstdint>
#include <math.h>

// ---------------------------------------------------------------------------
// Problem constants
// ---------------------------------------------------------------------------
#define NTOK   16384          // B*L
#define DMOD   1152           // D
#define D3C    384            // D/3
#define NHEAD  16
#define DK3C   24
#define ROWS3  (NTOK * 3)     // 49152
#define SCORE_SCALE 0.1178511301977579f   // 1/sqrt(72)

#define W4SZ   (D3C * D3C)            // 147456
#define WOSZ   (DMOD * DMOD)          // 1327104
#define WO_OFF (4 * W4SZ)             // 589824

// ---------------------------------------------------------------------------
// Scratch
// ---------------------------------------------------------------------------
__device__ float g_xn[NTOK * DMOD];           // tf32-rounded LN output
__device__ float g_proj[4][ROWS3 * D3C];      // q,k,v,gate (fp32)
__device__ float g_hout[NTOK * DMOD];         // tf32-rounded attention output
__device__ float g_wt[WO_OFF + WOSZ];         // tf32-rounded weights

// ---------------------------------------------------------------------------
// Helpers
// ---------------------------------------------------------------------------
__device__ __forceinline__ uint32_t f2tf32(float f) {
    uint32_t u;
    asm("cvt.rna.tf32.f32 %0, %1;" : "=r"(u) : "f"(f));
    return u;
}
__device__ __forceinline__ uint32_t smem_u32(const void* p) {
    uint32_t a;
    asm("{ .reg .u64 t; cvta.to.shared.u64 t, %1; cvt.u32.u64 %0, t; }" : "=r"(a) : "l"(p));
    return a;
}
__device__ __forceinline__ void cp_async16(uint32_t dst, const void* src) {
    asm volatile("cp.async.cg.shared.global [%0], [%1], 16;" :: "r"(dst), "l"(src));
}
__device__ __forceinline__ void cp_commit() {
    asm volatile("cp.async.commit_group;" ::: "memory");
}
template<int N>
__device__ __forceinline__ void cp_wait() {
    asm volatile("cp.async.wait_group %0;" :: "n"(N) : "memory");
}
__device__ __forceinline__ void mma_tf32(float* d, const uint32_t* a, const uint32_t* b) {
    asm volatile(
        "mma.sync.aligned.m16n8k8.row.col.f32.tf32.tf32.f32 "
        "{%0,%1,%2,%3}, {%4,%5,%6,%7}, {%8,%9}, {%0,%1,%2,%3};"
        : "+f"(d[0]), "+f"(d[1]), "+f"(d[2]), "+f"(d[3])
        : "r"(a[0]), "r"(a[1]), "r"(a[2]), "r"(a[3]), "r"(b[0]), "r"(b[1]));
}

// ---------------------------------------------------------------------------
// Kernel 1: LayerNorm (output rounded to tf32)
// ---------------------------------------------------------------------------
__global__ void ln_kernel(const float* __restrict__ x,
                          const float* __restrict__ gamma,
                          const float* __restrict__ beta,
                          float* __restrict__ xn) {
    const int n = blockIdx.x;
    const int t = threadIdx.x;
    const float4* xr = reinterpret_cast<const float4*>(x + (size_t)n * DMOD);
    float4 v = xr[t];
    float s  = v.x + v.y + v.z + v.w;
    float ss = v.x * v.x + v.y * v.y + v.z * v.z + v.w * v.w;
    #pragma unroll
    for (int off = 16; off > 0; off >>= 1) {
        s  += __shfl_xor_sync(0xffffffffu, s,  off);
        ss += __shfl_xor_sync(0xffffffffu, ss, off);
    }
    __shared__ float red_s[9], red_ss[9], stat[2];
    const int warp = t >> 5, lane = t & 31;
    if (lane == 0) { red_s[warp] = s; red_ss[warp] = ss; }
    __syncthreads();
    if (t == 0) {
        float ts = 0.f, tss = 0.f;
        #pragma unroll
        for (int i = 0; i < 9; i++) { ts += red_s[i]; tss += red_ss[i]; }
        float mu  = ts * (1.0f / DMOD);
        float var = tss * (1.0f / DMOD) - mu * mu;
        stat[0] = mu; stat[1] = rsqrtf(var + 1e-6f);
    }
    __syncthreads();
    const float mu = stat[0], rstd = stat[1];
    const float4 gm = reinterpret_cast<const float4*>(gamma)[t];
    const float4 be = reinterpret_cast<const float4*>(beta)[t];
    float4 o;
    o.x = __uint_as_float(f2tf32((v.x - mu) * rstd * gm.x + be.x));
    o.y = __uint_as_float(f2tf32((v.y - mu) * rstd * gm.y + be.y));
    o.z = __uint_as_float(f2tf32((v.z - mu) * rstd * gm.z + be.z));
    o.w = __uint_as_float(f2tf32((v.w - mu) * rstd * gm.w + be.w));
    reinterpret_cast<float4*>(xn + (size_t)n * DMOD)[t] = o;
}

// ---------------------------------------------------------------------------
// Kernel 1b: round weights to tf32 into g_wt
// ---------------------------------------------------------------------------
__global__ void prep_w(const float* __restrict__ Wq, const float* __restrict__ Wk,
                       const float* __restrict__ Wv, const float* __restrict__ Wg,
                       const float* __restrict__ Wo) {
    const int total = WO_OFF + WOSZ;
    for (int i = blockIdx.x * blockDim.x + threadIdx.x; i < total; i += gridDim.x * blockDim.x) {
        float v;
        if (i < WO_OFF) {
            const int z = i / W4SZ, r = i % W4SZ;
            const float* W = (z == 0) ? Wq : (z == 1) ? Wk : (z == 2) ? Wv : Wg;
            v = W[r];
        } else {
            v = Wo[i - WO_OFF];
        }
        g_wt[i] = __uint_as_float(f2tf32(v));
    }
}

// ---------------------------------------------------------------------------
// tf32 mma.sync GEMM: C[M,Ntot] = A[M,KD] @ W[Ntot,KD]^T + bias (+resid*g)
// Block tile 256x128x16, 256 threads, 8 warps (4x2), warp tile 64x64.
// 4-stage cp.async pipeline, one __syncthreads per k-chunk.
// ---------------------------------------------------------------------------
struct GemmPtrs {
    const float* bias[4];
    float*       C[4];
    const float* W[4];
    const float* resid;
    const float* g;
};

#define PITCH  20                 // floats per smem row (16 data + 4 pad)
#define LROWS  384                // 256 A rows + 128 B rows per stage
#define SSF    (LROWS * PITCH)    // floats per stage (7680)
#define NSTG   4

template<int KD, bool RES>
__global__ __launch_bounds__(256)
void mma_gemm(const float* __restrict__ A, GemmPtrs gp, int Ntot) {
    constexpr int NC = KD / 16;
    extern __shared__ float sm[];       // [NSTG][SSF]

    const int tid  = threadIdx.x;
    const int wid  = tid >> 5;
    const int lane = tid & 31;
    const int g    = lane >> 2;     // groupID
    const int t4   = lane & 3;      // threadID_in_group
    const int wm0  = (wid >> 1) * 64;   // 0..192
    const int wn0  = (wid & 1) * 64;    // 0 or 64
    const int z    = blockIdx.z;

    const float* W    = gp.W[z];
    const float* bias = gp.bias[z];
    float*       C    = gp.C[z];
    const int bm = blockIdx.y * 256;
    const int bn = blockIdx.x * 128;

    const uint32_t smaddr = smem_u32(sm);

    // Each thread owns 6 float4 slots per stage: idx = tid + t*256,
    // row = idx>>2 (0..255 -> A, 256..383 -> B), j = idx&3 (k sub-offset).
    auto load_stage = [&](int c) {
        const int s  = c & (NSTG - 1);
        const int k0 = c * 16;
        const uint32_t sb = smaddr + (uint32_t)(s * SSF) * 4u;
        #pragma unroll
        for (int t = 0; t < 6; t++) {
            const int idx = tid + t * 256;
            const int row = idx >> 2;
            const int j   = idx & 3;
            const float* src = (row < 256)
                ? (A + (size_t)(bm + row) * KD + k0 + j * 4)
                : (W + (size_t)(bn + row - 256) * KD + k0 + j * 4);
            cp_async16(sb + (uint32_t)(row * PITCH + j * 4) * 4u, src);
        }
        cp_commit();
    };

    float acc[4][8][4];
    #pragma unroll
    for (int i = 0; i < 4; i++)
        #pragma unroll
        for (int j = 0; j < 8; j++)
            #pragma unroll
            for (int r = 0; r < 4; r++) acc[i][j][r] = 0.f;

    load_stage(0);
    load_stage(1);
    load_stage(2);

    for (int c = 0; c < NC; c++) {
        if (c < NC - 2)      cp_wait<2>();
        else if (c == NC - 2) cp_wait<1>();
        else                  cp_wait<0>();
        __syncthreads();
        if (c + 3 < NC) load_stage(c + 3);

        const float* S  = sm + (c & (NSTG - 1)) * SSF;
        const float* As = S;
        const float* Bs = S + 256 * PITCH;

        #pragma unroll
        for (int kk = 0; kk < 2; kk++) {
            const int kb = kk * 8;
            uint32_t afr[4][4];
            #pragma unroll
            for (int ms = 0; ms < 4; ms++) {
                const int r = wm0 + ms * 16 + g;
                afr[ms][0] = __float_as_uint(As[(r    ) * PITCH + kb + t4    ]);
                afr[ms][1] = __float_as_uint(As[(r + 8) * PITCH + kb + t4    ]);
                afr[ms][2] = __float_as_uint(As[(r    ) * PITCH + kb + t4 + 4]);
                afr[ms][3] = __float_as_uint(As[(r + 8) * PITCH + kb + t4 + 4]);
            }
            #pragma unroll
            for (int ns = 0; ns < 8; ns++) {
                const int n = wn0 + ns * 8 + g;
                uint32_t bfr[2];
                bfr[0] = __float_as_uint(Bs[n * PITCH + kb + t4    ]);
                bfr[1] = __float_as_uint(Bs[n * PITCH + kb + t4 + 4]);
                #pragma unroll
                for (int ms = 0; ms < 4; ms++)
                    mma_tf32(acc[ms][ns], afr[ms], bfr);
            }
        }
    }

    // Epilogue
    const float gval = RES ? __ldg(gp.g) : 0.f;
    #pragma unroll
    for (int ms = 0; ms < 4; ms++) {
        const int row0 = bm + wm0 + ms * 16 + g;
        #pragma unroll
        for (int ns = 0; ns < 8; ns++) {
            const int col = bn + wn0 + ns * 8 + 2 * t4;
            const float b0 = __ldg(bias + col);
            const float b1 = __ldg(bias + col + 1);
            float o0 = acc[ms][ns][0] + b0;
            float o1 = acc[ms][ns][1] + b1;
            float o2 = acc[ms][ns][2] + b0;
            float o3 = acc[ms][ns][3] + b1;
            if (RES) {
                const float* r0 = gp.resid + (size_t)row0 * Ntot + col;
                const float* r1 = gp.resid + (size_t)(row0 + 8) * Ntot + col;
                o0 = fmaf(r0[0], gval, o0);
                o1 = fmaf(r0[1], gval, o1);
                o2 = fmaf(r1[0], gval, o2);
                o3 = fmaf(r1[1], gval, o3);
            }
            *reinterpret_cast<float2*>(C + (size_t)row0 * Ntot + col)       = make_float2(o0, o1);
            *reinterpret_cast<float2*>(C + (size_t)(row0 + 8) * Ntot + col) = make_float2(o2, o3);
        }
    }
}

// ---------------------------------------------------------------------------
// Attention + gate (output rounded to tf32 for GEMM2)
// ---------------------------------------------------------------------------
__global__ void attn_kernel() {
    const int gwarp = (blockIdx.x * blockDim.x + threadIdx.x) >> 5;
    const int lane  = threadIdx.x & 31;
    const int n = gwarp / NHEAD;
    const int h = gwarp % NHEAD;
    const bool act = lane < DK3C;
    const int d = act ? lane : 0;
    const int off = h * DK3C + d;

    float q[3], k[3], v[3], gt[3];
    #pragma unroll
    for (int i = 0; i < 3; i++) {
        const size_t idx = (size_t)(n * 3 + i) * D3C + off;
        q[i]  = act ? g_proj[0][idx] : 0.f;
        k[i]  = act ? g_proj[1][idx] : 0.f;
        v[i]  = act ? g_proj[2][idx] : 0.f;
        gt[i] = act ? g_proj[3][idx] : 0.f;
    }
    float s[3][3];
    #pragma unroll
    for (int i = 0; i < 3; i++)
        #pragma unroll
        for (int j = 0; j < 3; j++) {
            float p = q[i] * k[j];
            #pragma unroll
            for (int om = 16; om > 0; om >>= 1)
                p += __shfl_xor_sync(0xffffffffu, p, om);
            s[i][j] = p * SCORE_SCALE;
        }
    #pragma unroll
    for (int i = 0; i < 3; i++) {
        float m = fmaxf(s[i][0], fmaxf(s[i][1], s[i][2]));
        float e0 = expf(s[i][0] - m), e1 = expf(s[i][1] - m), e2 = expf(s[i][2] - m);
        float inv = 1.0f / (e0 + e1 + e2);
        float o = (e0 * v[0] + e1 * v[1] + e2 * v[2]) * inv;
        o *= 1.0f / (1.0f + expf(-gt[i]));
        if (act)
            g_hout[(size_t)n * DMOD + i * D3C + off] = __uint_as_float(f2tf32(o));
    }
}

// ---------------------------------------------------------------------------
// Launch
// ---------------------------------------------------------------------------
extern "C" void kernel_launch(void* const* d_in, const int* in_sizes, int n_in,
                              void* d_out, int out_size) {
    const float* x    = (const float*)d_in[0];
    const float* ln_g = (const float*)d_in[1];
    const float* ln_b = (const float*)d_in[2];
    const float* Wq   = (const float*)d_in[3];
    const float* bq   = (const float*)d_in[4];
    const float* Wk   = (const float*)d_in[5];
    const float* bk   = (const float*)d_in[6];
    const float* Wv   = (const float*)d_in[7];
    const float* bv   = (const float*)d_in[8];
    const float* Wg   = (const float*)d_in[9];
    const float* bg   = (const float*)d_in[10];
    const float* Wo   = (const float*)d_in[11];
    const float* bo   = (const float*)d_in[12];
    const float* gsc  = (const float*)d_in[13];
    float* out = (float*)d_out;

    float *p_xn, *p_proj, *p_hout, *p_wt;
    cudaGetSymbolAddress((void**)&p_xn,   g_xn);
    cudaGetSymbolAddress((void**)&p_proj, g_proj);
    cudaGetSymbolAddress((void**)&p_hout, g_hout);
    cudaGetSymbolAddress((void**)&p_wt,   g_wt);

    const int SMEM_BYTES = NSTG * SSF * 4;   // 4 * 7680 * 4 = 122880
    cudaFuncSetAttribute((const void*)mma_gemm<D3C, false>,
                         cudaFuncAttributeMaxDynamicSharedMemorySize, SMEM_BYTES);
    cudaFuncSetAttribute((const void*)mma_gemm<DMOD, true>,
                         cudaFuncAttributeMaxDynamicSharedMemorySize, SMEM_BYTES);

    // 1) LayerNorm + weight prep
    ln_kernel<<<NTOK, 288>>>(x, ln_g, ln_b, p_xn);
    prep_w<<<296, 256>>>(Wq, Wk, Wv, Wg, Wo);

    // 2) Four projection GEMMs (grid.z): [49152,384] @ [384,384]^T
    {
        GemmPtrs gp;
        gp.bias[0] = bq; gp.bias[1] = bk; gp.bias[2] = bv; gp.bias[3] = bg;
        for (int zz = 0; zz < 4; zz++) {
            gp.C[zz] = p_proj + (size_t)zz * ROWS3 * D3C;
            gp.W[zz] = p_wt + (size_t)zz * W4SZ;
        }
        gp.resid = nullptr; gp.g = nullptr;
        dim3 grid(D3C / 128, ROWS3 / 256, 4);   // (3, 192, 4)
        mma_gemm<D3C, false><<<grid, 256, SMEM_BYTES>>>(p_xn, gp, D3C);
    }

    // 3) Attention + gate
    attn_kernel<<<NTOK * NHEAD * 32 / 256, 256>>>();

    // 4) Output GEMM + bias + residual*g : [16384,1152] @ [1152,1152]^T
    {
        GemmPtrs gp;
        gp.bias[0] = bo; gp.C[0] = out; gp.W[0] = p_wt + WO_OFF;
        gp.bias[1] = gp.bias[2] = gp.bias[3] = nullptr;
        gp.C[1] = gp.C[2] = gp.C[3] = nullptr;
        gp.W[1] = gp.W[2] = gp.W[3] = nullptr;
        gp.resid = x; gp.g = gsc;
        dim3 grid(DMOD / 128, NTOK / 256, 1);   // (9, 64, 1)
        mma_gemm<DMOD, true><<<grid, 256, SMEM_BYTES>>>(p_hout, gp, DMOD);
    }
}

// round 5
// speedup vs baseline: 3.4128x; 1.3401x over previous
#include <cuda_runtime.h>
#include <cuda_bf16.h>
#include <cstdint>
#include <math.h>

// ---------------------------------------------------------------------------
// Problem constants
// ---------------------------------------------------------------------------
#define NTOK   16384          // B*L
#define DMOD   1152           // D
#define D3C    384            // D/3
#define NHEAD  16
#define DK3C   24
#define ROWS3  (NTOK * 3)     // 49152
#define SCORE_SCALE 0.1178511301977579f   // 1/sqrt(72)

#define W4SZ   (D3C * D3C)            // 147456 floats per proj weight
#define WOSZ   (DMOD * DMOD)          // 1327104
#define WO_OFF (4 * W4SZ)             // 589824
#define WT_WORDS ((WO_OFF + WOSZ) / 2)

// ---------------------------------------------------------------------------
// Scratch (bf16x2 packed as u32 words where noted)
// ---------------------------------------------------------------------------
__device__ __align__(16) uint32_t g_xn[NTOK * DMOD / 2];        // LN out, bf16x2
__device__ __align__(16) float    g_proj[4][ROWS3 * D3C];       // q,k,v,gate fp32
__device__ __align__(16) __nv_bfloat16 g_hout[NTOK * DMOD];     // attn out, bf16
__device__ __align__(16) uint32_t g_wt[WT_WORDS];               // weights, bf16x2

// ---------------------------------------------------------------------------
// Helpers
// ---------------------------------------------------------------------------
__device__ __forceinline__ uint32_t pack_bf16x2(float lo, float hi) {
    uint32_t r;
    asm("cvt.rn.bf16x2.f32 %0, %1, %2;" : "=r"(r) : "f"(hi), "f"(lo));
    return r;
}
__device__ __forceinline__ uint32_t smem_u32(const void* p) {
    uint32_t a;
    asm("{ .reg .u64 t; cvta.to.shared.u64 t, %1; cvt.u32.u64 %0, t; }" : "=r"(a) : "l"(p));
    return a;
}
__device__ __forceinline__ void cp_async16(uint32_t dst, const void* src) {
    asm volatile("cp.async.cg.shared.global [%0], [%1], 16;" :: "r"(dst), "l"(src));
}
__device__ __forceinline__ void cp_commit() {
    asm volatile("cp.async.commit_group;" ::: "memory");
}
template<int N>
__device__ __forceinline__ void cp_wait() {
    asm volatile("cp.async.wait_group %0;" :: "n"(N) : "memory");
}
__device__ __forceinline__ void mma_bf16(float* d, const uint32_t* a, const uint32_t* b) {
    asm volatile(
        "mma.sync.aligned.m16n8k16.row.col.f32.bf16.bf16.f32 "
        "{%0,%1,%2,%3}, {%4,%5,%6,%7}, {%8,%9}, {%0,%1,%2,%3};"
        : "+f"(d[0]), "+f"(d[1]), "+f"(d[2]), "+f"(d[3])
        : "r"(a[0]), "r"(a[1]), "r"(a[2]), "r"(a[3]), "r"(b[0]), "r"(b[1]));
}

// ---------------------------------------------------------------------------
// Kernel 1: LayerNorm -> bf16x2
// ---------------------------------------------------------------------------
__global__ void ln_kernel(const float* __restrict__ x,
                          const float* __restrict__ gamma,
                          const float* __restrict__ beta,
                          uint32_t* __restrict__ xn) {
    const int n = blockIdx.x;
    const int t = threadIdx.x;                   // 0..287
    const float4* xr = reinterpret_cast<const float4*>(x + (size_t)n * DMOD);
    float4 v = xr[t];
    float s  = v.x + v.y + v.z + v.w;
    float ss = v.x * v.x + v.y * v.y + v.z * v.z + v.w * v.w;
    #pragma unroll
    for (int off = 16; off > 0; off >>= 1) {
        s  += __shfl_xor_sync(0xffffffffu, s,  off);
        ss += __shfl_xor_sync(0xffffffffu, ss, off);
    }
    __shared__ float red_s[9], red_ss[9], stat[2];
    const int warp = t >> 5, lane = t & 31;
    if (lane == 0) { red_s[warp] = s; red_ss[warp] = ss; }
    __syncthreads();
    if (t == 0) {
        float ts = 0.f, tss = 0.f;
        #pragma unroll
        for (int i = 0; i < 9; i++) { ts += red_s[i]; tss += red_ss[i]; }
        float mu  = ts * (1.0f / DMOD);
        float var = tss * (1.0f / DMOD) - mu * mu;
        stat[0] = mu; stat[1] = rsqrtf(var + 1e-6f);
    }
    __syncthreads();
    const float mu = stat[0], rstd = stat[1];
    const float4 gm = reinterpret_cast<const float4*>(gamma)[t];
    const float4 be = reinterpret_cast<const float4*>(beta)[t];
    uint2 o;
    o.x = pack_bf16x2((v.x - mu) * rstd * gm.x + be.x, (v.y - mu) * rstd * gm.y + be.y);
    o.y = pack_bf16x2((v.z - mu) * rstd * gm.z + be.z, (v.w - mu) * rstd * gm.w + be.w);
    reinterpret_cast<uint2*>(xn + (size_t)n * (DMOD / 2))[t] = o;
}

// ---------------------------------------------------------------------------
// Kernel 1b: weights fp32 -> bf16x2 words
// ---------------------------------------------------------------------------
__global__ void prep_w(const float* __restrict__ Wq, const float* __restrict__ Wk,
                       const float* __restrict__ Wv, const float* __restrict__ Wg,
                       const float* __restrict__ Wo) {
    for (int i = blockIdx.x * blockDim.x + threadIdx.x; i < WT_WORDS;
         i += gridDim.x * blockDim.x) {
        float lo, hi;
        if (i < WO_OFF / 2) {
            const int z = i / (W4SZ / 2), r = i % (W4SZ / 2);
            const float* W = (z == 0) ? Wq : (z == 1) ? Wk : (z == 2) ? Wv : Wg;
            lo = W[2 * r]; hi = W[2 * r + 1];
        } else {
            const int j = i - WO_OFF / 2;
            lo = Wo[2 * j]; hi = Wo[2 * j + 1];
        }
        g_wt[i] = pack_bf16x2(lo, hi);
    }
}

// ---------------------------------------------------------------------------
// bf16 mma.sync GEMM: C[M,Ntot] = A[M,KD] @ W[Ntot,KD]^T + bias (+resid*g)
// A, W given as bf16x2 u32 words (KD/2 words per row).
// Block tile 256x128x16, 256 threads, 8 warps (4x2), warp tile 64x64.
// 4-stage cp.async pipeline. PITCH=12 u32 -> conflict-free fragment LDS.
// ---------------------------------------------------------------------------
struct GemmPtrs {
    const float*    bias[4];
    float*          C[4];
    const uint32_t* W[4];
    const float*    resid;
    const float*    g;
};

#define PITCH  12                 // u32 words per smem row (8 data + 4 pad)
#define LROWS  384                // 256 A rows + 128 B rows per stage
#define SSW    (LROWS * PITCH)    // u32 words per stage (4608)
#define NSTG   4

template<int KD, bool RES>
__global__ __launch_bounds__(256)
void mma_gemm(const uint32_t* __restrict__ A, GemmPtrs gp, int Ntot) {
    constexpr int KW = KD / 2;          // u32 words per gmem row
    constexpr int NC = KD / 16;         // k-chunks
    extern __shared__ uint32_t sm[];    // [NSTG][SSW]

    const int tid  = threadIdx.x;
    const int wid  = tid >> 5;
    const int lane = tid & 31;
    const int g    = lane >> 2;
    const int t4   = lane & 3;
    const int wm0  = (wid >> 1) * 64;
    const int wn0  = (wid & 1) * 64;
    const int z    = blockIdx.z;

    const uint32_t* W    = gp.W[z];
    const float*    bias = gp.bias[z];
    float*          C    = gp.C[z];
    const int bm = blockIdx.y * 256;
    const int bn = blockIdx.x * 128;

    const uint32_t smaddr = smem_u32(sm);

    // 3 cp.async16 per thread per stage: idx = tid + t*256 in [0,768)
    // row = idx>>1 (0..255 A, 256..383 B), half = idx&1 selects 16B.
    auto load_stage = [&](int c) {
        const int s  = c & (NSTG - 1);
        const int k0 = c * 8;                  // u32 word offset in gmem row
        const uint32_t sb = smaddr + (uint32_t)(s * SSW) * 4u;
        #pragma unroll
        for (int t = 0; t < 3; t++) {
            const int idx  = tid + t * 256;
            const int row  = idx >> 1;
            const int half = idx & 1;
            const uint32_t* src = (row < 256)
                ? (A + (size_t)(bm + row) * KW + k0 + half * 4)
                : (W + (size_t)(bn + row - 256) * KW + k0 + half * 4);
            cp_async16(sb + (uint32_t)(row * PITCH + half * 4) * 4u, src);
        }
        cp_commit();
    };

    float acc[4][8][4];
    #pragma unroll
    for (int i = 0; i < 4; i++)
        #pragma unroll
        for (int j = 0; j < 8; j++)
            #pragma unroll
            for (int r = 0; r < 4; r++) acc[i][j][r] = 0.f;

    load_stage(0);
    load_stage(1);
    load_stage(2);

    for (int c = 0; c < NC; c++) {
        if (c < NC - 2)       cp_wait<2>();
        else if (c == NC - 2) cp_wait<1>();
        else                  cp_wait<0>();
        __syncthreads();
        if (c + 3 < NC) load_stage(c + 3);

        const uint32_t* S  = sm + (c & (NSTG - 1)) * SSW;
        const uint32_t* As = S;
        const uint32_t* Bs = S + 256 * PITCH;

        uint32_t afr[4][4];
        #pragma unroll
        for (int ms = 0; ms < 4; ms++) {
            const int r = wm0 + ms * 16 + g;
            afr[ms][0] = As[(r    ) * PITCH + t4    ];
            afr[ms][1] = As[(r + 8) * PITCH + t4    ];
            afr[ms][2] = As[(r    ) * PITCH + t4 + 4];
            afr[ms][3] = As[(r + 8) * PITCH + t4 + 4];
        }
        #pragma unroll
        for (int ns = 0; ns < 8; ns++) {
            const int n = wn0 + ns * 8 + g;
            uint32_t bfr[2];
            bfr[0] = Bs[n * PITCH + t4    ];
            bfr[1] = Bs[n * PITCH + t4 + 4];
            #pragma unroll
            for (int ms = 0; ms < 4; ms++)
                mma_bf16(acc[ms][ns], afr[ms], bfr);
        }
    }

    // Epilogue
    const float gval = RES ? __ldg(gp.g) : 0.f;
    #pragma unroll
    for (int ms = 0; ms < 4; ms++) {
        const int row0 = bm + wm0 + ms * 16 + g;
        #pragma unroll
        for (int ns = 0; ns < 8; ns++) {
            const int col = bn + wn0 + ns * 8 + 2 * t4;
            const float b0 = __ldg(bias + col);
            const float b1 = __ldg(bias + col + 1);
            float o0 = acc[ms][ns][0] + b0;
            float o1 = acc[ms][ns][1] + b1;
            float o2 = acc[ms][ns][2] + b0;
            float o3 = acc[ms][ns][3] + b1;
            if (RES) {
                const float* r0 = gp.resid + (size_t)row0 * Ntot + col;
                const float* r1 = gp.resid + (size_t)(row0 + 8) * Ntot + col;
                o0 = fmaf(r0[0], gval, o0);
                o1 = fmaf(r0[1], gval, o1);
                o2 = fmaf(r1[0], gval, o2);
                o3 = fmaf(r1[1], gval, o3);
            }
            *reinterpret_cast<float2*>(C + (size_t)row0 * Ntot + col)       = make_float2(o0, o1);
            *reinterpret_cast<float2*>(C + (size_t)(row0 + 8) * Ntot + col) = make_float2(o2, o3);
        }
    }
}

// ---------------------------------------------------------------------------
// Attention + gate -> bf16 output for GEMM2
// ---------------------------------------------------------------------------
__global__ void attn_kernel() {
    const int gwarp = (blockIdx.x * blockDim.x + threadIdx.x) >> 5;
    const int lane  = threadIdx.x & 31;
    const int n = gwarp / NHEAD;
    const int h = gwarp % NHEAD;
    const bool act = lane < DK3C;
    const int d = act ? lane : 0;
    const int off = h * DK3C + d;

    float q[3], k[3], v[3], gt[3];
    #pragma unroll
    for (int i = 0; i < 3; i++) {
        const size_t idx = (size_t)(n * 3 + i) * D3C + off;
        q[i]  = act ? g_proj[0][idx] : 0.f;
        k[i]  = act ? g_proj[1][idx] : 0.f;
        v[i]  = act ? g_proj[2][idx] : 0.f;
        gt[i] = act ? g_proj[3][idx] : 0.f;
    }
    float s[3][3];
    #pragma unroll
    for (int i = 0; i < 3; i++)
        #pragma unroll
        for (int j = 0; j < 3; j++) {
            float p = q[i] * k[j];
            #pragma unroll
            for (int om = 16; om > 0; om >>= 1)
                p += __shfl_xor_sync(0xffffffffu, p, om);
            s[i][j] = p * SCORE_SCALE;
        }
    #pragma unroll
    for (int i = 0; i < 3; i++) {
        float m = fmaxf(s[i][0], fmaxf(s[i][1], s[i][2]));
        float e0 = expf(s[i][0] - m), e1 = expf(s[i][1] - m), e2 = expf(s[i][2] - m);
        float inv = 1.0f / (e0 + e1 + e2);
        float o = (e0 * v[0] + e1 * v[1] + e2 * v[2]) * inv;
        o *= 1.0f / (1.0f + expf(-gt[i]));
        if (act)
            g_hout[(size_t)n * DMOD + i * D3C + off] = __float2bfloat16_rn(o);
    }
}

// ---------------------------------------------------------------------------
// Launch
// ---------------------------------------------------------------------------
extern "C" void kernel_launch(void* const* d_in, const int* in_sizes, int n_in,
                              void* d_out, int out_size) {
    const float* x    = (const float*)d_in[0];
    const float* ln_g = (const float*)d_in[1];
    const float* ln_b = (const float*)d_in[2];
    const float* Wq   = (const float*)d_in[3];
    const float* bq   = (const float*)d_in[4];
    const float* Wk   = (const float*)d_in[5];
    const float* bk   = (const float*)d_in[6];
    const float* Wv   = (const float*)d_in[7];
    const float* bv   = (const float*)d_in[8];
    const float* Wg   = (const float*)d_in[9];
    const float* bg   = (const float*)d_in[10];
    const float* Wo   = (const float*)d_in[11];
    const float* bo   = (const float*)d_in[12];
    const float* gsc  = (const float*)d_in[13];
    float* out = (float*)d_out;

    uint32_t *p_xn, *p_wt;
    float *p_proj;
    __nv_bfloat16* p_hout;
    cudaGetSymbolAddress((void**)&p_xn,   g_xn);
    cudaGetSymbolAddress((void**)&p_proj, g_proj);
    cudaGetSymbolAddress((void**)&p_hout, g_hout);
    cudaGetSymbolAddress((void**)&p_wt,   g_wt);

    const int SMEM_BYTES = NSTG * SSW * 4;   // 4 * 4608 * 4 = 73728
    cudaFuncSetAttribute((const void*)mma_gemm<D3C, false>,
                         cudaFuncAttributeMaxDynamicSharedMemorySize, SMEM_BYTES);
    cudaFuncSetAttribute((const void*)mma_gemm<DMOD, true>,
                         cudaFuncAttributeMaxDynamicSharedMemorySize, SMEM_BYTES);

    // 1) LayerNorm + weight prep
    ln_kernel<<<NTOK, 288>>>(x, ln_g, ln_b, p_xn);
    prep_w<<<296, 256>>>(Wq, Wk, Wv, Wg, Wo);

    // 2) Four projection GEMMs (grid.z): [49152,384] @ [384,384]^T
    {
        GemmPtrs gp;
        gp.bias[0] = bq; gp.bias[1] = bk; gp.bias[2] = bv; gp.bias[3] = bg;
        for (int zz = 0; zz < 4; zz++) {
            gp.C[zz] = p_proj + (size_t)zz * ROWS3 * D3C;
            gp.W[zz] = p_wt + (size_t)zz * (W4SZ / 2);
        }
        gp.resid = nullptr; gp.g = nullptr;
        dim3 grid(D3C / 128, ROWS3 / 256, 4);   // (3, 192, 4)
        mma_gemm<D3C, false><<<grid, 256, SMEM_BYTES>>>(p_xn, gp, D3C);
    }

    // 3) Attention + gate
    attn_kernel<<<NTOK * NHEAD * 32 / 256, 256>>>();

    // 4) Output GEMM + bias + residual*g : [16384,1152] @ [1152,1152]^T
    {
        GemmPtrs gp;
        gp.bias[0] = bo; gp.C[0] = out; gp.W[0] = p_wt + WO_OFF / 2;
        gp.bias[1] = gp.bias[2] = gp.bias[3] = nullptr;
        gp.C[1] = gp.C[2] = gp.C[3] = nullptr;
        gp.W[1] = gp.W[2] = gp.W[3] = nullptr;
        gp.resid = x; gp.g = gsc;
        dim3 grid(DMOD / 128, NTOK / 256, 1);   // (9, 64, 1)
        mma_gemm<DMOD, true><<<grid, 256, SMEM_BYTES>>>(
            reinterpret_cast<const uint32_t*>(p_hout), gp, DMOD);
    }
}

// round 6
// speedup vs baseline: 3.5933x; 1.0529x over previous
#include <cuda_runtime.h>
#include <cuda_bf16.h>
#include <cstdint>
#include <math.h>

// ---------------------------------------------------------------------------
// Problem constants
// ---------------------------------------------------------------------------
#define NTOK   16384          // B*L
#define DMOD   1152           // D
#define D3C    384            // D/3
#define NHEAD  16
#define DK3C   24
#define ROWS3  (NTOK * 3)     // 49152
#define SCORE_SCALE 0.1178511301977579f   // 1/sqrt(72)

#define W4SZ   (D3C * D3C)            // floats per proj weight
#define WOSZ   (DMOD * DMOD)
#define WO_OFF (4 * W4SZ)
#define WT_WORDS ((WO_OFF + WOSZ) / 2)

// ---------------------------------------------------------------------------
// Scratch
// ---------------------------------------------------------------------------
__device__ __align__(16) uint32_t g_xn[NTOK * DMOD / 2];          // LN out, bf16x2
__device__ __align__(16) __nv_bfloat16 g_proj[4][ROWS3 * D3C];    // q,k,v,gate bf16
__device__ __align__(16) __nv_bfloat16 g_hout[NTOK * DMOD];       // attn out, bf16
__device__ __align__(16) uint32_t g_wt[WT_WORDS];                 // weights, bf16x2

// ---------------------------------------------------------------------------
// Helpers
// ---------------------------------------------------------------------------
__device__ __forceinline__ uint32_t pack_bf16x2(float lo, float hi) {
    uint32_t r;
    asm("cvt.rn.bf16x2.f32 %0, %1, %2;" : "=r"(r) : "f"(hi), "f"(lo));
    return r;
}
__device__ __forceinline__ uint32_t smem_u32(const void* p) {
    uint32_t a;
    asm("{ .reg .u64 t; cvta.to.shared.u64 t, %1; cvt.u32.u64 %0, t; }" : "=r"(a) : "l"(p));
    return a;
}
__device__ __forceinline__ void cp_async16(uint32_t dst, const void* src) {
    asm volatile("cp.async.cg.shared.global [%0], [%1], 16;" :: "r"(dst), "l"(src));
}
__device__ __forceinline__ void cp_commit() {
    asm volatile("cp.async.commit_group;" ::: "memory");
}
template<int N>
__device__ __forceinline__ void cp_wait() {
    asm volatile("cp.async.wait_group %0;" :: "n"(N) : "memory");
}
__device__ __forceinline__ void mma_bf16(float* d, const uint32_t* a, const uint32_t* b) {
    asm volatile(
        "mma.sync.aligned.m16n8k16.row.col.f32.bf16.bf16.f32 "
        "{%0,%1,%2,%3}, {%4,%5,%6,%7}, {%8,%9}, {%0,%1,%2,%3};"
        : "+f"(d[0]), "+f"(d[1]), "+f"(d[2]), "+f"(d[3])
        : "r"(a[0]), "r"(a[1]), "r"(a[2]), "r"(a[3]), "r"(b[0]), "r"(b[1]));
}
__device__ __forceinline__ void ldmatrix_x4(uint32_t* r, uint32_t addr) {
    asm volatile("ldmatrix.sync.aligned.m8n8.x4.shared.b16 {%0,%1,%2,%3}, [%4];"
        : "=r"(r[0]), "=r"(r[1]), "=r"(r[2]), "=r"(r[3]) : "r"(addr));
}

// ---------------------------------------------------------------------------
// Kernel 1: LayerNorm -> bf16x2
// ---------------------------------------------------------------------------
__global__ void ln_kernel(const float* __restrict__ x,
                          const float* __restrict__ gamma,
                          const float* __restrict__ beta,
                          uint32_t* __restrict__ xn) {
    const int n = blockIdx.x;
    const int t = threadIdx.x;
    const float4* xr = reinterpret_cast<const float4*>(x + (size_t)n * DMOD);
    float4 v = xr[t];
    float s  = v.x + v.y + v.z + v.w;
    float ss = v.x * v.x + v.y * v.y + v.z * v.z + v.w * v.w;
    #pragma unroll
    for (int off = 16; off > 0; off >>= 1) {
        s  += __shfl_xor_sync(0xffffffffu, s,  off);
        ss += __shfl_xor_sync(0xffffffffu, ss, off);
    }
    __shared__ float red_s[9], red_ss[9], stat[2];
    const int warp = t >> 5, lane = t & 31;
    if (lane == 0) { red_s[warp] = s; red_ss[warp] = ss; }
    __syncthreads();
    if (t == 0) {
        float ts = 0.f, tss = 0.f;
        #pragma unroll
        for (int i = 0; i < 9; i++) { ts += red_s[i]; tss += red_ss[i]; }
        float mu  = ts * (1.0f / DMOD);
        float var = tss * (1.0f / DMOD) - mu * mu;
        stat[0] = mu; stat[1] = rsqrtf(var + 1e-6f);
    }
    __syncthreads();
    const float mu = stat[0], rstd = stat[1];
    const float4 gm = reinterpret_cast<const float4*>(gamma)[t];
    const float4 be = reinterpret_cast<const float4*>(beta)[t];
    uint2 o;
    o.x = pack_bf16x2((v.x - mu) * rstd * gm.x + be.x, (v.y - mu) * rstd * gm.y + be.y);
    o.y = pack_bf16x2((v.z - mu) * rstd * gm.z + be.z, (v.w - mu) * rstd * gm.w + be.w);
    reinterpret_cast<uint2*>(xn + (size_t)n * (DMOD / 2))[t] = o;
}

// ---------------------------------------------------------------------------
// Kernel 1b: weights fp32 -> bf16x2
// ---------------------------------------------------------------------------
__global__ void prep_w(const float* __restrict__ Wq, const float* __restrict__ Wk,
                       const float* __restrict__ Wv, const float* __restrict__ Wg,
                       const float* __restrict__ Wo) {
    for (int i = blockIdx.x * blockDim.x + threadIdx.x; i < WT_WORDS;
         i += gridDim.x * blockDim.x) {
        float lo, hi;
        if (i < WO_OFF / 2) {
            const int z = i / (W4SZ / 2), r = i % (W4SZ / 2);
            const float* W = (z == 0) ? Wq : (z == 1) ? Wk : (z == 2) ? Wv : Wg;
            lo = W[2 * r]; hi = W[2 * r + 1];
        } else {
            const int j = i - WO_OFF / 2;
            lo = Wo[2 * j]; hi = Wo[2 * j + 1];
        }
        g_wt[i] = pack_bf16x2(lo, hi);
    }
}

// ---------------------------------------------------------------------------
// bf16 mma.sync GEMM with ldmatrix fragment loads.
// Block tile 256x128x16, 256 threads, warp tile 64x64, 4-stage cp.async.
// OUTB: write C as packed bf16x2; else fp32 (+ bias, optional resid*g).
// ---------------------------------------------------------------------------
struct GemmPtrs {
    const float*    bias[4];
    void*           C[4];
    const uint32_t* W[4];
    const float*    resid;
    const float*    g;
};

#define PITCH  12                 // u32 words per smem row (8 data + 4 pad)
#define LROWS  384
#define SSW    (LROWS * PITCH)
#define NSTG   4

template<int KD, bool RES, bool OUTB>
__global__ __launch_bounds__(256)
void mma_gemm(const uint32_t* __restrict__ A, GemmPtrs gp, int Ntot) {
    constexpr int KW = KD / 2;
    constexpr int NC = KD / 16;
    extern __shared__ uint32_t sm[];

    const int tid  = threadIdx.x;
    const int wid  = tid >> 5;
    const int lane = tid & 31;
    const int g    = lane >> 2;
    const int t4   = lane & 3;
    const int wm0  = (wid >> 1) * 64;
    const int wn0  = (wid & 1) * 64;
    const int z    = blockIdx.z;

    const uint32_t* W    = gp.W[z];
    const float*    bias = gp.bias[z];
    const int bm = blockIdx.y * 256;
    const int bn = blockIdx.x * 128;

    const uint32_t smaddr = smem_u32(sm);

    // ldmatrix per-thread addresses (byte offsets within a stage).
    // A x4 (per ms): rows wm0+ms*16+(lane&15), k-word half by lane>=16.
    uint32_t adrA[4];
    #pragma unroll
    for (int ms = 0; ms < 4; ms++) {
        const int row = wm0 + ms * 16 + (lane & 15);
        const int wof = ((lane >> 4) & 1) * 4;
        adrA[ms] = (uint32_t)(row * PITCH + wof) * 4u;
    }
    // B x4 (per ps, covering ns=2ps, 2ps+1):
    //   t0-7: rows n0..n0+7 words 0 | t8-15: same rows words 4
    //   t16-23: rows n0+8..15 words 0 | t24-31: rows+8 words 4
    uint32_t adrB[4];
    #pragma unroll
    for (int ps = 0; ps < 4; ps++) {
        const int row = wn0 + ps * 16 + (lane & 7) + ((lane >> 4) & 1) * 8;
        const int wof = ((lane >> 3) & 1) * 4;
        adrB[ps] = (uint32_t)(256 * PITCH + row * PITCH + wof) * 4u;
    }

    auto load_stage = [&](int c) {
        const int s  = c & (NSTG - 1);
        const int k0 = c * 8;
        const uint32_t sb = smaddr + (uint32_t)(s * SSW) * 4u;
        #pragma unroll
        for (int t = 0; t < 3; t++) {
            const int idx  = tid + t * 256;
            const int row  = idx >> 1;
            const int half = idx & 1;
            const uint32_t* src = (row < 256)
                ? (A + (size_t)(bm + row) * KW + k0 + half * 4)
                : (W + (size_t)(bn + row - 256) * KW + k0 + half * 4);
            cp_async16(sb + (uint32_t)(row * PITCH + half * 4) * 4u, src);
        }
        cp_commit();
    };

    float acc[4][8][4];
    #pragma unroll
    for (int i = 0; i < 4; i++)
        #pragma unroll
        for (int j = 0; j < 8; j++)
            #pragma unroll
            for (int r = 0; r < 4; r++) acc[i][j][r] = 0.f;

    load_stage(0);
    load_stage(1);
    load_stage(2);

    for (int c = 0; c < NC; c++) {
        if (c < NC - 2)       cp_wait<2>();
        else if (c == NC - 2) cp_wait<1>();
        else                  cp_wait<0>();
        __syncthreads();
        if (c + 3 < NC) load_stage(c + 3);

        const uint32_t sbase = smaddr + (uint32_t)((c & (NSTG - 1)) * SSW) * 4u;

        uint32_t afr[4][4];
        #pragma unroll
        for (int ms = 0; ms < 4; ms++)
            ldmatrix_x4(afr[ms], sbase + adrA[ms]);

        #pragma unroll
        for (int ps = 0; ps < 4; ps++) {
            uint32_t bfr[4];
            ldmatrix_x4(bfr, sbase + adrB[ps]);
            #pragma unroll
            for (int ms = 0; ms < 4; ms++) {
                mma_bf16(acc[ms][2 * ps],     afr[ms], bfr);
                mma_bf16(acc[ms][2 * ps + 1], afr[ms], bfr + 2);
            }
        }
    }

    // Epilogue
    const float gval = RES ? __ldg(gp.g) : 0.f;
    #pragma unroll
    for (int ms = 0; ms < 4; ms++) {
        const int row0 = bm + wm0 + ms * 16 + g;
        #pragma unroll
        for (int ns = 0; ns < 8; ns++) {
            const int col = bn + wn0 + ns * 8 + 2 * t4;
            const float b0 = __ldg(bias + col);
            const float b1 = __ldg(bias + col + 1);
            float o0 = acc[ms][ns][0] + b0;
            float o1 = acc[ms][ns][1] + b1;
            float o2 = acc[ms][ns][2] + b0;
            float o3 = acc[ms][ns][3] + b1;
            if (RES) {
                const float* r0 = gp.resid + (size_t)row0 * Ntot + col;
                const float* r1 = gp.resid + (size_t)(row0 + 8) * Ntot + col;
                o0 = fmaf(r0[0], gval, o0);
                o1 = fmaf(r0[1], gval, o1);
                o2 = fmaf(r1[0], gval, o2);
                o3 = fmaf(r1[1], gval, o3);
            }
            if (OUTB) {
                uint32_t* Cw = (uint32_t*)gp.C[z];
                Cw[(size_t)row0 * (Ntot / 2) + (col >> 1)]       = pack_bf16x2(o0, o1);
                Cw[(size_t)(row0 + 8) * (Ntot / 2) + (col >> 1)] = pack_bf16x2(o2, o3);
            } else {
                float* C = (float*)gp.C[z];
                *reinterpret_cast<float2*>(C + (size_t)row0 * Ntot + col)       = make_float2(o0, o1);
                *reinterpret_cast<float2*>(C + (size_t)(row0 + 8) * Ntot + col) = make_float2(o2, o3);
            }
        }
    }
}

// ---------------------------------------------------------------------------
// Attention + gate: bf16 inputs -> bf16 output
// ---------------------------------------------------------------------------
__global__ void attn_kernel() {
    const int gwarp = (blockIdx.x * blockDim.x + threadIdx.x) >> 5;
    const int lane  = threadIdx.x & 31;
    const int n = gwarp / NHEAD;
    const int h = gwarp % NHEAD;
    const bool act = lane < DK3C;
    const int d = act ? lane : 0;
    const int off = h * DK3C + d;

    float q[3], k[3], v[3], gt[3];
    #pragma unroll
    for (int i = 0; i < 3; i++) {
        const size_t idx = (size_t)(n * 3 + i) * D3C + off;
        q[i]  = act ? __bfloat162float(g_proj[0][idx]) : 0.f;
        k[i]  = act ? __bfloat162float(g_proj[1][idx]) : 0.f;
        v[i]  = act ? __bfloat162float(g_proj[2][idx]) : 0.f;
        gt[i] = act ? __bfloat162float(g_proj[3][idx]) : 0.f;
    }
    float s[3][3];
    #pragma unroll
    for (int i = 0; i < 3; i++)
        #pragma unroll
        for (int j = 0; j < 3; j++) {
            float p = q[i] * k[j];
            #pragma unroll
            for (int om = 16; om > 0; om >>= 1)
                p += __shfl_xor_sync(0xffffffffu, p, om);
            s[i][j] = p * SCORE_SCALE;
        }
    #pragma unroll
    for (int i = 0; i < 3; i++) {
        float m = fmaxf(s[i][0], fmaxf(s[i][1], s[i][2]));
        float e0 = expf(s[i][0] - m), e1 = expf(s[i][1] - m), e2 = expf(s[i][2] - m);
        float inv = 1.0f / (e0 + e1 + e2);
        float o = (e0 * v[0] + e1 * v[1] + e2 * v[2]) * inv;
        o *= 1.0f / (1.0f + expf(-gt[i]));
        if (act)
            g_hout[(size_t)n * DMOD + i * D3C + off] = __float2bfloat16_rn(o);
    }
}

// ---------------------------------------------------------------------------
// Launch
// ---------------------------------------------------------------------------
extern "C" void kernel_launch(void* const* d_in, const int* in_sizes, int n_in,
                              void* d_out, int out_size) {
    const float* x    = (const float*)d_in[0];
    const float* ln_g = (const float*)d_in[1];
    const float* ln_b = (const float*)d_in[2];
    const float* Wq   = (const float*)d_in[3];
    const float* bq   = (const float*)d_in[4];
    const float* Wk   = (const float*)d_in[5];
    const float* bk   = (const float*)d_in[6];
    const float* Wv   = (const float*)d_in[7];
    const float* bv   = (const float*)d_in[8];
    const float* Wg   = (const float*)d_in[9];
    const float* bg   = (const float*)d_in[10];
    const float* Wo   = (const float*)d_in[11];
    const float* bo   = (const float*)d_in[12];
    const float* gsc  = (const float*)d_in[13];
    float* out = (float*)d_out;

    uint32_t *p_xn, *p_wt;
    __nv_bfloat16 *p_proj, *p_hout;
    cudaGetSymbolAddress((void**)&p_xn,   g_xn);
    cudaGetSymbolAddress((void**)&p_proj, g_proj);
    cudaGetSymbolAddress((void**)&p_hout, g_hout);
    cudaGetSymbolAddress((void**)&p_wt,   g_wt);

    const int SMEM_BYTES = NSTG * SSW * 4;   // 73728
    cudaFuncSetAttribute((const void*)mma_gemm<D3C, false, true>,
                         cudaFuncAttributeMaxDynamicSharedMemorySize, SMEM_BYTES);
    cudaFuncSetAttribute((const void*)mma_gemm<DMOD, true, false>,
                         cudaFuncAttributeMaxDynamicSharedMemorySize, SMEM_BYTES);

    // 1) LayerNorm + weight prep
    ln_kernel<<<NTOK, 288>>>(x, ln_g, ln_b, p_xn);
    prep_w<<<296, 256>>>(Wq, Wk, Wv, Wg, Wo);

    // 2) Four projection GEMMs (grid.z): [49152,384] @ [384,384]^T -> bf16
    {
        GemmPtrs gp;
        gp.bias[0] = bq; gp.bias[1] = bk; gp.bias[2] = bv; gp.bias[3] = bg;
        for (int zz = 0; zz < 4; zz++) {
            gp.C[zz] = p_proj + (size_t)zz * ROWS3 * D3C;
            gp.W[zz] = p_wt + (size_t)zz * (W4SZ / 2);
        }
        gp.resid = nullptr; gp.g = nullptr;
        dim3 grid(D3C / 128, ROWS3 / 256, 4);
        mma_gemm<D3C, false, true><<<grid, 256, SMEM_BYTES>>>(p_xn, gp, D3C);
    }

    // 3) Attention + gate
    attn_kernel<<<NTOK * NHEAD * 32 / 256, 256>>>();

    // 4) Output GEMM + bias + residual*g -> fp32
    {
        GemmPtrs gp;
        gp.bias[0] = bo; gp.C[0] = out; gp.W[0] = p_wt + WO_OFF / 2;
        gp.bias[1] = gp.bias[2] = gp.bias[3] = nullptr;
        gp.C[1] = gp.C[2] = gp.C[3] = nullptr;
        gp.W[1] = gp.W[2] = gp.W[3] = nullptr;
        gp.resid = x; gp.g = gsc;
        dim3 grid(DMOD / 128, NTOK / 256, 1);
        mma_gemm<DMOD, true, false><<<grid, 256, SMEM_BYTES>>>(
            reinterpret_cast<const uint32_t*>(p_hout), gp, DMOD);
    }
}

// round 7
// speedup vs baseline: 3.9374x; 1.0958x over previous
#include <cuda_runtime.h>
#include <cuda_bf16.h>
#include <cstdint>
#include <math.h>

// ---------------------------------------------------------------------------
// Problem constants
// ---------------------------------------------------------------------------
#define NTOK   16384          // B*L
#define DMOD   1152           // D
#define D3C    384            // D/3
#define NHEAD  16
#define DK3C   24
#define ROWS3  (NTOK * 3)     // 49152
#define SCORE_SCALE 0.1178511301977579f   // 1/sqrt(72)

#define W4SZ   (D3C * D3C)
#define WOSZ   (DMOD * DMOD)
#define WO_OFF (4 * W4SZ)
#define WT_WORDS ((WO_OFF + WOSZ) / 2)

// ---------------------------------------------------------------------------
// Scratch
// ---------------------------------------------------------------------------
__device__ __align__(16) uint32_t g_xn[NTOK * DMOD / 2];          // LN out, bf16x2
__device__ __align__(16) __nv_bfloat16 g_proj[4][ROWS3 * D3C];    // q,k,v,gate bf16
__device__ __align__(16) __nv_bfloat16 g_hout[NTOK * DMOD];       // attn out, bf16
__device__ __align__(16) uint32_t g_wt[WT_WORDS];                 // weights, bf16x2

// ---------------------------------------------------------------------------
// Helpers
// ---------------------------------------------------------------------------
__device__ __forceinline__ uint32_t pack_bf16x2(float lo, float hi) {
    uint32_t r;
    asm("cvt.rn.bf16x2.f32 %0, %1, %2;" : "=r"(r) : "f"(hi), "f"(lo));
    return r;
}
__device__ __forceinline__ uint32_t smem_u32(const void* p) {
    uint32_t a;
    asm("{ .reg .u64 t; cvta.to.shared.u64 t, %1; cvt.u32.u64 %0, t; }" : "=r"(a) : "l"(p));
    return a;
}
__device__ __forceinline__ void cp_async16(uint32_t dst, const void* src) {
    asm volatile("cp.async.cg.shared.global [%0], [%1], 16;" :: "r"(dst), "l"(src));
}
__device__ __forceinline__ void cp_commit() {
    asm volatile("cp.async.commit_group;" ::: "memory");
}
template<int N>
__device__ __forceinline__ void cp_wait() {
    asm volatile("cp.async.wait_group %0;" :: "n"(N) : "memory");
}
__device__ __forceinline__ void mma_bf16(float* d, const uint32_t* a, const uint32_t* b) {
    asm volatile(
        "mma.sync.aligned.m16n8k16.row.col.f32.bf16.bf16.f32 "
        "{%0,%1,%2,%3}, {%4,%5,%6,%7}, {%8,%9}, {%0,%1,%2,%3};"
        : "+f"(d[0]), "+f"(d[1]), "+f"(d[2]), "+f"(d[3])
        : "r"(a[0]), "r"(a[1]), "r"(a[2]), "r"(a[3]), "r"(b[0]), "r"(b[1]));
}
__device__ __forceinline__ void ldmatrix_x4(uint32_t* r, uint32_t addr) {
    asm volatile("ldmatrix.sync.aligned.m8n8.x4.shared.b16 {%0,%1,%2,%3}, [%4];"
        : "=r"(r[0]), "=r"(r[1]), "=r"(r[2]), "=r"(r[3]) : "r"(addr));
}
// Convert uint4 (8 bf16) -> 8 floats
__device__ __forceinline__ void bf8_to_f(const uint4& u, float* f) {
    const __nv_bfloat162* p = reinterpret_cast<const __nv_bfloat162*>(&u);
    #pragma unroll
    for (int i = 0; i < 4; i++) {
        float2 v = __bfloat1622float2(p[i]);
        f[2 * i] = v.x; f[2 * i + 1] = v.y;
    }
}

// ---------------------------------------------------------------------------
// Kernel 1: LayerNorm -> bf16x2
// ---------------------------------------------------------------------------
__global__ void ln_kernel(const float* __restrict__ x,
                          const float* __restrict__ gamma,
                          const float* __restrict__ beta,
                          uint32_t* __restrict__ xn) {
    const int n = blockIdx.x;
    const int t = threadIdx.x;
    const float4* xr = reinterpret_cast<const float4*>(x + (size_t)n * DMOD);
    float4 v = xr[t];
    float s  = v.x + v.y + v.z + v.w;
    float ss = v.x * v.x + v.y * v.y + v.z * v.z + v.w * v.w;
    #pragma unroll
    for (int off = 16; off > 0; off >>= 1) {
        s  += __shfl_xor_sync(0xffffffffu, s,  off);
        ss += __shfl_xor_sync(0xffffffffu, ss, off);
    }
    __shared__ float red_s[9], red_ss[9], stat[2];
    const int warp = t >> 5, lane = t & 31;
    if (lane == 0) { red_s[warp] = s; red_ss[warp] = ss; }
    __syncthreads();
    if (t == 0) {
        float ts = 0.f, tss = 0.f;
        #pragma unroll
        for (int i = 0; i < 9; i++) { ts += red_s[i]; tss += red_ss[i]; }
        float mu  = ts * (1.0f / DMOD);
        float var = tss * (1.0f / DMOD) - mu * mu;
        stat[0] = mu; stat[1] = rsqrtf(var + 1e-6f);
    }
    __syncthreads();
    const float mu = stat[0], rstd = stat[1];
    const float4 gm = reinterpret_cast<const float4*>(gamma)[t];
    const float4 be = reinterpret_cast<const float4*>(beta)[t];
    uint2 o;
    o.x = pack_bf16x2((v.x - mu) * rstd * gm.x + be.x, (v.y - mu) * rstd * gm.y + be.y);
    o.y = pack_bf16x2((v.z - mu) * rstd * gm.z + be.z, (v.w - mu) * rstd * gm.w + be.w);
    reinterpret_cast<uint2*>(xn + (size_t)n * (DMOD / 2))[t] = o;
}

// ---------------------------------------------------------------------------
// Kernel 1b: weights fp32 -> bf16x2
// ---------------------------------------------------------------------------
__global__ void prep_w(const float* __restrict__ Wq, const float* __restrict__ Wk,
                       const float* __restrict__ Wv, const float* __restrict__ Wg,
                       const float* __restrict__ Wo) {
    for (int i = blockIdx.x * blockDim.x + threadIdx.x; i < WT_WORDS;
         i += gridDim.x * blockDim.x) {
        float lo, hi;
        if (i < WO_OFF / 2) {
            const int z = i / (W4SZ / 2), r = i % (W4SZ / 2);
            const float* W = (z == 0) ? Wq : (z == 1) ? Wk : (z == 2) ? Wv : Wg;
            lo = W[2 * r]; hi = W[2 * r + 1];
        } else {
            const int j = i - WO_OFF / 2;
            lo = Wo[2 * j]; hi = Wo[2 * j + 1];
        }
        g_wt[i] = pack_bf16x2(lo, hi);
    }
}

// ---------------------------------------------------------------------------
// bf16 mma.sync GEMM (unchanged from round 6)
// ---------------------------------------------------------------------------
struct GemmPtrs {
    const float*    bias[4];
    void*           C[4];
    const uint32_t* W[4];
    const float*    resid;
    const float*    g;
};

#define PITCH  12
#define LROWS  384
#define SSW    (LROWS * PITCH)
#define NSTG   4

template<int KD, bool RES, bool OUTB>
__global__ __launch_bounds__(256)
void mma_gemm(const uint32_t* __restrict__ A, GemmPtrs gp, int Ntot) {
    constexpr int KW = KD / 2;
    constexpr int NC = KD / 16;
    extern __shared__ uint32_t sm[];

    const int tid  = threadIdx.x;
    const int wid  = tid >> 5;
    const int lane = tid & 31;
    const int g    = lane >> 2;
    const int t4   = lane & 3;
    const int wm0  = (wid >> 1) * 64;
    const int wn0  = (wid & 1) * 64;
    const int z    = blockIdx.z;

    const uint32_t* W    = gp.W[z];
    const float*    bias = gp.bias[z];
    const int bm = blockIdx.y * 256;
    const int bn = blockIdx.x * 128;

    const uint32_t smaddr = smem_u32(sm);

    uint32_t adrA[4];
    #pragma unroll
    for (int ms = 0; ms < 4; ms++) {
        const int row = wm0 + ms * 16 + (lane & 15);
        const int wof = ((lane >> 4) & 1) * 4;
        adrA[ms] = (uint32_t)(row * PITCH + wof) * 4u;
    }
    uint32_t adrB[4];
    #pragma unroll
    for (int ps = 0; ps < 4; ps++) {
        const int row = wn0 + ps * 16 + (lane & 7) + ((lane >> 4) & 1) * 8;
        const int wof = ((lane >> 3) & 1) * 4;
        adrB[ps] = (uint32_t)(256 * PITCH + row * PITCH + wof) * 4u;
    }

    auto load_stage = [&](int c) {
        const int s  = c & (NSTG - 1);
        const int k0 = c * 8;
        const uint32_t sb = smaddr + (uint32_t)(s * SSW) * 4u;
        #pragma unroll
        for (int t = 0; t < 3; t++) {
            const int idx  = tid + t * 256;
            const int row  = idx >> 1;
            const int half = idx & 1;
            const uint32_t* src = (row < 256)
                ? (A + (size_t)(bm + row) * KW + k0 + half * 4)
                : (W + (size_t)(bn + row - 256) * KW + k0 + half * 4);
            cp_async16(sb + (uint32_t)(row * PITCH + half * 4) * 4u, src);
        }
        cp_commit();
    };

    float acc[4][8][4];
    #pragma unroll
    for (int i = 0; i < 4; i++)
        #pragma unroll
        for (int j = 0; j < 8; j++)
            #pragma unroll
            for (int r = 0; r < 4; r++) acc[i][j][r] = 0.f;

    load_stage(0);
    load_stage(1);
    load_stage(2);

    for (int c = 0; c < NC; c++) {
        if (c < NC - 2)       cp_wait<2>();
        else if (c == NC - 2) cp_wait<1>();
        else                  cp_wait<0>();
        __syncthreads();
        if (c + 3 < NC) load_stage(c + 3);

        const uint32_t sbase = smaddr + (uint32_t)((c & (NSTG - 1)) * SSW) * 4u;

        uint32_t afr[4][4];
        #pragma unroll
        for (int ms = 0; ms < 4; ms++)
            ldmatrix_x4(afr[ms], sbase + adrA[ms]);

        #pragma unroll
        for (int ps = 0; ps < 4; ps++) {
            uint32_t bfr[4];
            ldmatrix_x4(bfr, sbase + adrB[ps]);
            #pragma unroll
            for (int ms = 0; ms < 4; ms++) {
                mma_bf16(acc[ms][2 * ps],     afr[ms], bfr);
                mma_bf16(acc[ms][2 * ps + 1], afr[ms], bfr + 2);
            }
        }
    }

    const float gval = RES ? __ldg(gp.g) : 0.f;
    #pragma unroll
    for (int ms = 0; ms < 4; ms++) {
        const int row0 = bm + wm0 + ms * 16 + g;
        #pragma unroll
        for (int ns = 0; ns < 8; ns++) {
            const int col = bn + wn0 + ns * 8 + 2 * t4;
            const float b0 = __ldg(bias + col);
            const float b1 = __ldg(bias + col + 1);
            float o0 = acc[ms][ns][0] + b0;
            float o1 = acc[ms][ns][1] + b1;
            float o2 = acc[ms][ns][2] + b0;
            float o3 = acc[ms][ns][3] + b1;
            if (RES) {
                const float* r0 = gp.resid + (size_t)row0 * Ntot + col;
                const float* r1 = gp.resid + (size_t)(row0 + 8) * Ntot + col;
                o0 = fmaf(r0[0], gval, o0);
                o1 = fmaf(r0[1], gval, o1);
                o2 = fmaf(r1[0], gval, o2);
                o3 = fmaf(r1[1], gval, o3);
            }
            if (OUTB) {
                uint32_t* Cw = (uint32_t*)gp.C[z];
                Cw[(size_t)row0 * (Ntot / 2) + (col >> 1)]       = pack_bf16x2(o0, o1);
                Cw[(size_t)(row0 + 8) * (Ntot / 2) + (col >> 1)] = pack_bf16x2(o2, o3);
            } else {
                float* C = (float*)gp.C[z];
                *reinterpret_cast<float2*>(C + (size_t)row0 * Ntot + col)       = make_float2(o0, o1);
                *reinterpret_cast<float2*>(C + (size_t)(row0 + 8) * Ntot + col) = make_float2(o2, o3);
            }
        }
    }
}

// ---------------------------------------------------------------------------
// Attention + gate: ONE THREAD per (token, head). No shuffles, softmax once.
// q/k/v/gate at g_proj[p][(n*3+i)*384 + h*24 + d]; chunks of 8 bf16 = uint4.
// ---------------------------------------------------------------------------
__global__ void attn_kernel() {
    const int t = blockIdx.x * blockDim.x + threadIdx.x;   // 0 .. NTOK*NHEAD-1
    const int n = t >> 4;
    const int h = t & 15;
    const size_t ebase = (size_t)n * 3 * D3C + h * DK3C;   // element offset

    const uint4* q4 = reinterpret_cast<const uint4*>(&g_proj[0][ebase]);
    const uint4* k4 = reinterpret_cast<const uint4*>(&g_proj[1][ebase]);
    const uint4* v4 = reinterpret_cast<const uint4*>(&g_proj[2][ebase]);
    const uint4* g4 = reinterpret_cast<const uint4*>(&g_proj[3][ebase]);
    // uint4 stride per group i: D3C bf16 = 768B = 48 uint4

    // ---- scores ----
    float s[3][3] = {{0.f,0.f,0.f},{0.f,0.f,0.f},{0.f,0.f,0.f}};
    #pragma unroll
    for (int c = 0; c < 3; c++) {
        float qf[3][8], kf[3][8];
        #pragma unroll
        for (int i = 0; i < 3; i++) {
            bf8_to_f(q4[i * 48 + c], qf[i]);
            bf8_to_f(k4[i * 48 + c], kf[i]);
        }
        #pragma unroll
        for (int i = 0; i < 3; i++)
            #pragma unroll
            for (int j = 0; j < 3; j++) {
                float p = 0.f;
                #pragma unroll
                for (int d = 0; d < 8; d++) p = fmaf(qf[i][d], kf[j][d], p);
                s[i][j] += p;
            }
    }

    // ---- softmax over j (once!) ----
    float a[3][3];
    #pragma unroll
    for (int i = 0; i < 3; i++) {
        float s0 = s[i][0] * SCORE_SCALE, s1 = s[i][1] * SCORE_SCALE, s2 = s[i][2] * SCORE_SCALE;
        float m = fmaxf(s0, fmaxf(s1, s2));
        float e0 = expf(s0 - m), e1 = expf(s1 - m), e2 = expf(s2 - m);
        float inv = 1.0f / (e0 + e1 + e2);
        a[i][0] = e0 * inv; a[i][1] = e1 * inv; a[i][2] = e2 * inv;
    }

    // ---- output: (attn @ v) * sigmoid(gate), store bf16 ----
    const size_t obase = (size_t)n * DMOD + h * DK3C;      // + i*D3C + c*8
    #pragma unroll
    for (int c = 0; c < 3; c++) {
        float vf[3][8], gf[3][8];
        #pragma unroll
        for (int j = 0; j < 3; j++) bf8_to_f(v4[j * 48 + c], vf[j]);
        #pragma unroll
        for (int i = 0; i < 3; i++) bf8_to_f(g4[i * 48 + c], gf[i]);
        #pragma unroll
        for (int i = 0; i < 3; i++) {
            uint4 ou;
            uint32_t* ow = reinterpret_cast<uint32_t*>(&ou);
            #pragma unroll
            for (int p = 0; p < 4; p++) {
                float o0 = a[i][0] * vf[0][2*p]   + a[i][1] * vf[1][2*p]   + a[i][2] * vf[2][2*p];
                float o1 = a[i][0] * vf[0][2*p+1] + a[i][1] * vf[1][2*p+1] + a[i][2] * vf[2][2*p+1];
                o0 *= 1.0f / (1.0f + expf(-gf[i][2*p]));
                o1 *= 1.0f / (1.0f + expf(-gf[i][2*p+1]));
                ow[p] = pack_bf16x2(o0, o1);
            }
            *reinterpret_cast<uint4*>(&g_hout[obase + (size_t)i * D3C + c * 8]) = ou;
        }
    }
}

// ---------------------------------------------------------------------------
// Launch
// ---------------------------------------------------------------------------
extern "C" void kernel_launch(void* const* d_in, const int* in_sizes, int n_in,
                              void* d_out, int out_size) {
    const float* x    = (const float*)d_in[0];
    const float* ln_g = (const float*)d_in[1];
    const float* ln_b = (const float*)d_in[2];
    const float* Wq   = (const float*)d_in[3];
    const float* bq   = (const float*)d_in[4];
    const float* Wk   = (const float*)d_in[5];
    const float* bk   = (const float*)d_in[6];
    const float* Wv   = (const float*)d_in[7];
    const float* bv   = (const float*)d_in[8];
    const float* Wg   = (const float*)d_in[9];
    const float* bg   = (const float*)d_in[10];
    const float* Wo   = (const float*)d_in[11];
    const float* bo   = (const float*)d_in[12];
    const float* gsc  = (const float*)d_in[13];
    float* out = (float*)d_out;

    uint32_t *p_xn, *p_wt;
    __nv_bfloat16 *p_proj, *p_hout;
    cudaGetSymbolAddress((void**)&p_xn,   g_xn);
    cudaGetSymbolAddress((void**)&p_proj, g_proj);
    cudaGetSymbolAddress((void**)&p_hout, g_hout);
    cudaGetSymbolAddress((void**)&p_wt,   g_wt);

    const int SMEM_BYTES = NSTG * SSW * 4;   // 73728
    cudaFuncSetAttribute((const void*)mma_gemm<D3C, false, true>,
                         cudaFuncAttributeMaxDynamicSharedMemorySize, SMEM_BYTES);
    cudaFuncSetAttribute((const void*)mma_gemm<DMOD, true, false>,
                         cudaFuncAttributeMaxDynamicSharedMemorySize, SMEM_BYTES);

    // 1) LayerNorm + weight prep
    ln_kernel<<<NTOK, 288>>>(x, ln_g, ln_b, p_xn);
    prep_w<<<296, 256>>>(Wq, Wk, Wv, Wg, Wo);

    // 2) Four projection GEMMs (grid.z): [49152,384] @ [384,384]^T -> bf16
    {
        GemmPtrs gp;
        gp.bias[0] = bq; gp.bias[1] = bk; gp.bias[2] = bv; gp.bias[3] = bg;
        for (int zz = 0; zz < 4; zz++) {
            gp.C[zz] = p_proj + (size_t)zz * ROWS3 * D3C;
            gp.W[zz] = p_wt + (size_t)zz * (W4SZ / 2);
        }
        gp.resid = nullptr; gp.g = nullptr;
        dim3 grid(D3C / 128, ROWS3 / 256, 4);
        mma_gemm<D3C, false, true><<<grid, 256, SMEM_BYTES>>>(p_xn, gp, D3C);
    }

    // 3) Attention + gate: one thread per (n, h)
    attn_kernel<<<NTOK * NHEAD / 256, 256>>>();

    // 4) Output GEMM + bias + residual*g -> fp32
    {
        GemmPtrs gp;
        gp.bias[0] = bo; gp.C[0] = out; gp.W[0] = p_wt + WO_OFF / 2;
        gp.bias[1] = gp.bias[2] = gp.bias[3] = nullptr;
        gp.C[1] = gp.C[2] = gp.C[3] = nullptr;
        gp.W[1] = gp.W[2] = gp.W[3] = nullptr;
        gp.resid = x; gp.g = gsc;
        dim3 grid(DMOD / 128, NTOK / 256, 1);
        mma_gemm<DMOD, true, false><<<grid, 256, SMEM_BYTES>>>(
            reinterpret_cast<const uint32_t*>(p_hout), gp, DMOD);
    }
}

// round 10
// speedup vs baseline: 4.6225x; 1.1740x over previous
#include <cuda_runtime.h>
#include <cuda_bf16.h>
#include <cstdint>
#include <math.h>

// ---------------------------------------------------------------------------
// Problem constants
// ---------------------------------------------------------------------------
#define NTOK   16384          // B*L
#define DMOD   1152           // D
#define D3C    384            // D/3
#define NHEAD  16
#define DK3C   24
#define ROWS3  (NTOK * 3)     // 49152
#define SCORE_SCALE 0.1178511301977579f   // 1/sqrt(72)

#define W4SZ   (D3C * D3C)
#define WOSZ   (DMOD * DMOD)
#define WO_OFF (4 * W4SZ)
#define WT_WORDS ((WO_OFF + WOSZ) / 2)

// ---------------------------------------------------------------------------
// Scratch
// ---------------------------------------------------------------------------
__device__ __align__(16) uint32_t g_xn[NTOK * DMOD / 2];          // LN out, bf16x2
__device__ __align__(16) __nv_bfloat16 g_proj[4][ROWS3 * D3C];    // q,k,v,gate bf16
__device__ __align__(16) __nv_bfloat16 g_hout[NTOK * DMOD];       // attn out, bf16
__device__ __align__(16) uint32_t g_wt[WT_WORDS];                 // weights, bf16x2

// ---------------------------------------------------------------------------
// Helpers
// ---------------------------------------------------------------------------
__device__ __forceinline__ uint32_t pack_bf16x2(float lo, float hi) {
    uint32_t r;
    asm("cvt.rn.bf16x2.f32 %0, %1, %2;" : "=r"(r) : "f"(hi), "f"(lo));
    return r;
}
__device__ __forceinline__ uint32_t smem_u32(const void* p) {
    uint32_t a;
    asm("{ .reg .u64 t; cvta.to.shared.u64 t, %1; cvt.u32.u64 %0, t; }" : "=r"(a) : "l"(p));
    return a;
}
__device__ __forceinline__ void cp_async16(uint32_t dst, const void* src) {
    asm volatile("cp.async.cg.shared.global [%0], [%1], 16;" :: "r"(dst), "l"(src));
}
__device__ __forceinline__ void cp_commit() {
    asm volatile("cp.async.commit_group;" ::: "memory");
}
template<int N>
__device__ __forceinline__ void cp_wait() {
    asm volatile("cp.async.wait_group %0;" :: "n"(N) : "memory");
}
__device__ __forceinline__ void mma_bf16(float* d, const uint32_t* a, const uint32_t* b) {
    asm volatile(
        "mma.sync.aligned.m16n8k16.row.col.f32.bf16.bf16.f32 "
        "{%0,%1,%2,%3}, {%4,%5,%6,%7}, {%8,%9}, {%0,%1,%2,%3};"
        : "+f"(d[0]), "+f"(d[1]), "+f"(d[2]), "+f"(d[3])
        : "r"(a[0]), "r"(a[1]), "r"(a[2]), "r"(a[3]), "r"(b[0]), "r"(b[1]));
}
__device__ __forceinline__ void ldmatrix_x4(uint32_t* r, uint32_t addr) {
    asm volatile("ldmatrix.sync.aligned.m8n8.x4.shared.b16 {%0,%1,%2,%3}, [%4];"
        : "=r"(r[0]), "=r"(r[1]), "=r"(r[2]), "=r"(r[3]) : "r"(addr));
}
__device__ __forceinline__ void bf8_to_f(const uint4& u, float* f) {
    const __nv_bfloat162* p = reinterpret_cast<const __nv_bfloat162*>(&u);
    #pragma unroll
    for (int i = 0; i < 4; i++) {
        float2 v = __bfloat1622float2(p[i]);
        f[2 * i] = v.x; f[2 * i + 1] = v.y;
    }
}

// ---------------------------------------------------------------------------
// Kernel 1: LayerNorm -> bf16x2
// ---------------------------------------------------------------------------
__global__ void ln_kernel(const float* __restrict__ x,
                          const float* __restrict__ gamma,
                          const float* __restrict__ beta,
                          uint32_t* __restrict__ xn) {
    const int n = blockIdx.x;
    const int t = threadIdx.x;
    const float4* xr = reinterpret_cast<const float4*>(x + (size_t)n * DMOD);
    float4 v = xr[t];
    float s  = v.x + v.y + v.z + v.w;
    float ss = v.x * v.x + v.y * v.y + v.z * v.z + v.w * v.w;
    #pragma unroll
    for (int off = 16; off > 0; off >>= 1) {
        s  += __shfl_xor_sync(0xffffffffu, s,  off);
        ss += __shfl_xor_sync(0xffffffffu, ss, off);
    }
    __shared__ float red_s[9], red_ss[9], stat[2];
    const int warp = t >> 5, lane = t & 31;
    if (lane == 0) { red_s[warp] = s; red_ss[warp] = ss; }
    __syncthreads();
    if (t == 0) {
        float ts = 0.f, tss = 0.f;
        #pragma unroll
        for (int i = 0; i < 9; i++) { ts += red_s[i]; tss += red_ss[i]; }
        float mu  = ts * (1.0f / DMOD);
        float var = tss * (1.0f / DMOD) - mu * mu;
        stat[0] = mu; stat[1] = rsqrtf(var + 1e-6f);
    }
    __syncthreads();
    const float mu = stat[0], rstd = stat[1];
    const float4 gm = reinterpret_cast<const float4*>(gamma)[t];
    const float4 be = reinterpret_cast<const float4*>(beta)[t];
    uint2 o;
    o.x = pack_bf16x2((v.x - mu) * rstd * gm.x + be.x, (v.y - mu) * rstd * gm.y + be.y);
    o.y = pack_bf16x2((v.z - mu) * rstd * gm.z + be.z, (v.w - mu) * rstd * gm.w + be.w);
    reinterpret_cast<uint2*>(xn + (size_t)n * (DMOD / 2))[t] = o;
}

// ---------------------------------------------------------------------------
// Kernel 1b: weights fp32 -> bf16x2
// ---------------------------------------------------------------------------
__global__ void prep_w(const float* __restrict__ Wq, const float* __restrict__ Wk,
                       const float* __restrict__ Wv, const float* __restrict__ Wg,
                       const float* __restrict__ Wo) {
    for (int i = blockIdx.x * blockDim.x + threadIdx.x; i < WT_WORDS;
         i += gridDim.x * blockDim.x) {
        float lo, hi;
        if (i < WO_OFF / 2) {
            const int z = i / (W4SZ / 2), r = i % (W4SZ / 2);
            const float* W = (z == 0) ? Wq : (z == 1) ? Wk : (z == 2) ? Wv : Wg;
            lo = W[2 * r]; hi = W[2 * r + 1];
        } else {
            const int j = i - WO_OFF / 2;
            lo = Wo[2 * j]; hi = Wo[2 * j + 1];
        }
        g_wt[i] = pack_bf16x2(lo, hi);
    }
}

// ---------------------------------------------------------------------------
// bf16 mma.sync GEMM with ldmatrix.  Block 256x128, 8 warps, warp 64x64.
// K-chunk = 32 (16 u32 words per row), 4-stage cp.async pipeline,
// ONE barrier per 32-K (same loop shape as the validated 16-K version).
// ---------------------------------------------------------------------------
struct GemmPtrs {
    const float*    bias[4];
    void*           C[4];
    const uint32_t* W[4];
    const float*    resid;
    const float*    g;
};

#define PITCH  20                 // u32 words per smem row (16 data + 4 pad)
#define LROWS  384                // 256 A rows + 128 B rows per stage
#define SSW    (LROWS * PITCH)    // u32 words per stage (7680)
#define NSTG   4

template<int KD, bool RES, bool OUTB>
__global__ __launch_bounds__(256)
void mma_gemm(const uint32_t* __restrict__ A, GemmPtrs gp, int Ntot) {
    constexpr int KW = KD / 2;          // u32 words per gmem row
    constexpr int NC = KD / 32;         // 32-deep K chunks (12 or 36)
    extern __shared__ uint32_t sm[];

    const int tid  = threadIdx.x;
    const int wid  = tid >> 5;
    const int lane = tid & 31;
    const int g    = lane >> 2;
    const int t4   = lane & 3;
    const int wm0  = (wid >> 1) * 64;
    const int wn0  = (wid & 1) * 64;
    const int z    = blockIdx.z;

    const uint32_t* W    = gp.W[z];
    const float*    bias = gp.bias[z];
    const int bm = blockIdx.y * 256;
    const int bn = blockIdx.x * 128;

    const uint32_t smaddr = smem_u32(sm);

    // ldmatrix byte offsets within a stage (half u adds u*32 bytes = 8 words).
    uint32_t adrA[4];
    #pragma unroll
    for (int ms = 0; ms < 4; ms++) {
        const int row = wm0 + ms * 16 + (lane & 15);
        const int wof = ((lane >> 4) & 1) * 4;
        adrA[ms] = (uint32_t)(row * PITCH + wof) * 4u;
    }
    uint32_t adrB[4];
    #pragma unroll
    for (int ps = 0; ps < 4; ps++) {
        const int row = wn0 + ps * 16 + (lane & 7) + ((lane >> 4) & 1) * 8;
        const int wof = ((lane >> 3) & 1) * 4;
        adrB[ps] = (uint32_t)(256 * PITCH + row * PITCH + wof) * 4u;
    }

    // Load one 32-K chunk: 384 rows x 16 words; 6 cp.async16 per thread.
    auto load_stage = [&](int c) {
        const int s  = c & (NSTG - 1);
        const int k0 = c * 16;                 // u32 word offset in gmem row
        const uint32_t sb = smaddr + (uint32_t)(s * SSW) * 4u;
        #pragma unroll
        for (int t = 0; t < 6; t++) {
            const int idx = tid + t * 256;     // 0..1535
            const int row = idx >> 2;          // 0..383
            const int q   = idx & 3;           // 16B quarter within the row
            const uint32_t* src = (row < 256)
                ? (A + (size_t)(bm + row) * KW + k0 + q * 4)
                : (W + (size_t)(bn + row - 256) * KW + k0 + q * 4);
            cp_async16(sb + (uint32_t)(row * PITCH + q * 4) * 4u, src);
        }
        cp_commit();
    };

    float acc[4][8][4];
    #pragma unroll
    for (int i = 0; i < 4; i++)
        #pragma unroll
        for (int j = 0; j < 8; j++)
            #pragma unroll
            for (int r = 0; r < 4; r++) acc[i][j][r] = 0.f;

    load_stage(0);
    load_stage(1);
    load_stage(2);

    for (int c = 0; c < NC; c++) {
        if (c < NC - 2)       cp_wait<2>();
        else if (c == NC - 2) cp_wait<1>();
        else                  cp_wait<0>();
        __syncthreads();
        if (c + 3 < NC) load_stage(c + 3);

        const uint32_t sbase = smaddr + (uint32_t)((c & (NSTG - 1)) * SSW) * 4u;

        #pragma unroll
        for (int u = 0; u < 2; u++) {          // two 16-K halves of the chunk
            const uint32_t hbase = sbase + u * 32u;
            uint32_t afr[4][4];
            #pragma unroll
            for (int ms = 0; ms < 4; ms++)
                ldmatrix_x4(afr[ms], hbase + adrA[ms]);
            #pragma unroll
            for (int ps = 0; ps < 4; ps++) {
                uint32_t bfr[4];
                ldmatrix_x4(bfr, hbase + adrB[ps]);
                #pragma unroll
                for (int ms = 0; ms < 4; ms++) {
                    mma_bf16(acc[ms][2 * ps],     afr[ms], bfr);
                    mma_bf16(acc[ms][2 * ps + 1], afr[ms], bfr + 2);
                }
            }
        }
    }

    // Epilogue
    const float gval = RES ? __ldg(gp.g) : 0.f;
    #pragma unroll
    for (int ms = 0; ms < 4; ms++) {
        const int row0 = bm + wm0 + ms * 16 + g;
        #pragma unroll
        for (int ns = 0; ns < 8; ns++) {
            const int col = bn + wn0 + ns * 8 + 2 * t4;
            const float b0 = __ldg(bias + col);
            const float b1 = __ldg(bias + col + 1);
            float o0 = acc[ms][ns][0] + b0;
            float o1 = acc[ms][ns][1] + b1;
            float o2 = acc[ms][ns][2] + b0;
            float o3 = acc[ms][ns][3] + b1;
            if (RES) {
                const float* r0 = gp.resid + (size_t)row0 * Ntot + col;
                const float* r1 = gp.resid + (size_t)(row0 + 8) * Ntot + col;
                o0 = fmaf(r0[0], gval, o0);
                o1 = fmaf(r0[1], gval, o1);
                o2 = fmaf(r1[0], gval, o2);
                o3 = fmaf(r1[1], gval, o3);
            }
            if (OUTB) {
                uint32_t* Cw = (uint32_t*)gp.C[z];
                Cw[(size_t)row0 * (Ntot / 2) + (col >> 1)]       = pack_bf16x2(o0, o1);
                Cw[(size_t)(row0 + 8) * (Ntot / 2) + (col >> 1)] = pack_bf16x2(o2, o3);
            } else {
                float* C = (float*)gp.C[z];
                *reinterpret_cast<float2*>(C + (size_t)row0 * Ntot + col)       = make_float2(o0, o1);
                *reinterpret_cast<float2*>(C + (size_t)(row0 + 8) * Ntot + col) = make_float2(o2, o3);
            }
        }
    }
}

// ---------------------------------------------------------------------------
// Attention + gate: one thread per (token, head)
// ---------------------------------------------------------------------------
__global__ void attn_kernel() {
    const int t = blockIdx.x * blockDim.x + threadIdx.x;
    const int n = t >> 4;
    const int h = t & 15;
    const size_t ebase = (size_t)n * 3 * D3C + h * DK3C;

    const uint4* q4 = reinterpret_cast<const uint4*>(&g_proj[0][ebase]);
    const uint4* k4 = reinterpret_cast<const uint4*>(&g_proj[1][ebase]);
    const uint4* v4 = reinterpret_cast<const uint4*>(&g_proj[2][ebase]);
    const uint4* g4 = reinterpret_cast<const uint4*>(&g_proj[3][ebase]);

    float s[3][3] = {{0.f,0.f,0.f},{0.f,0.f,0.f},{0.f,0.f,0.f}};
    #pragma unroll
    for (int c = 0; c < 3; c++) {
        float qf[3][8], kf[3][8];
        #pragma unroll
        for (int i = 0; i < 3; i++) {
            bf8_to_f(q4[i * 48 + c], qf[i]);
            bf8_to_f(k4[i * 48 + c], kf[i]);
        }
        #pragma unroll
        for (int i = 0; i < 3; i++)
            #pragma unroll
            for (int j = 0; j < 3; j++) {
                float p = 0.f;
                #pragma unroll
                for (int d = 0; d < 8; d++) p = fmaf(qf[i][d], kf[j][d], p);
                s[i][j] += p;
            }
    }

    float a[3][3];
    #pragma unroll
    for (int i = 0; i < 3; i++) {
        float s0 = s[i][0] * SCORE_SCALE, s1 = s[i][1] * SCORE_SCALE, s2 = s[i][2] * SCORE_SCALE;
        float m = fmaxf(s0, fmaxf(s1, s2));
        float e0 = expf(s0 - m), e1 = expf(s1 - m), e2 = expf(s2 - m);
        float inv = 1.0f / (e0 + e1 + e2);
        a[i][0] = e0 * inv; a[i][1] = e1 * inv; a[i][2] = e2 * inv;
    }

    const size_t obase = (size_t)n * DMOD + h * DK3C;
    #pragma unroll
    for (int c = 0; c < 3; c++) {
        float vf[3][8], gf[3][8];
        #pragma unroll
        for (int j = 0; j < 3; j++) bf8_to_f(v4[j * 48 + c], vf[j]);
        #pragma unroll
        for (int i = 0; i < 3; i++) bf8_to_f(g4[i * 48 + c], gf[i]);
        #pragma unroll
        for (int i = 0; i < 3; i++) {
            uint4 ou;
            uint32_t* ow = reinterpret_cast<uint32_t*>(&ou);
            #pragma unroll
            for (int p = 0; p < 4; p++) {
                float o0 = a[i][0] * vf[0][2*p]   + a[i][1] * vf[1][2*p]   + a[i][2] * vf[2][2*p];
                float o1 = a[i][0] * vf[0][2*p+1] + a[i][1] * vf[1][2*p+1] + a[i][2] * vf[2][2*p+1];
                o0 *= 1.0f / (1.0f + expf(-gf[i][2*p]));
                o1 *= 1.0f / (1.0f + expf(-gf[i][2*p+1]));
                ow[p] = pack_bf16x2(o0, o1);
            }
            *reinterpret_cast<uint4*>(&g_hout[obase + (size_t)i * D3C + c * 8]) = ou;
        }
    }
}

// ---------------------------------------------------------------------------
// Launch
// ---------------------------------------------------------------------------
extern "C" void kernel_launch(void* const* d_in, const int* in_sizes, int n_in,
                              void* d_out, int out_size) {
    const float* x    = (const float*)d_in[0];
    const float* ln_g = (const float*)d_in[1];
    const float* ln_b = (const float*)d_in[2];
    const float* Wq   = (const float*)d_in[3];
    const float* bq   = (const float*)d_in[4];
    const float* Wk   = (const float*)d_in[5];
    const float* bk   = (const float*)d_in[6];
    const float* Wv   = (const float*)d_in[7];
    const float* bv   = (const float*)d_in[8];
    const float* Wg   = (const float*)d_in[9];
    const float* bg   = (const float*)d_in[10];
    const float* Wo   = (const float*)d_in[11];
    const float* bo   = (const float*)d_in[12];
    const float* gsc  = (const float*)d_in[13];
    float* out = (float*)d_out;

    uint32_t *p_xn, *p_wt;
    __nv_bfloat16 *p_proj, *p_hout;
    cudaGetSymbolAddress((void**)&p_xn,   g_xn);
    cudaGetSymbolAddress((void**)&p_proj, g_proj);
    cudaGetSymbolAddress((void**)&p_hout, g_hout);
    cudaGetSymbolAddress((void**)&p_wt,   g_wt);

    const int SMEM_BYTES = NSTG * SSW * 4;   // 4 * 7680 * 4 = 122880
    cudaFuncSetAttribute((const void*)mma_gemm<D3C, false, true>,
                         cudaFuncAttributeMaxDynamicSharedMemorySize, SMEM_BYTES);
    cudaFuncSetAttribute((const void*)mma_gemm<DMOD, true, false>,
                         cudaFuncAttributeMaxDynamicSharedMemorySize, SMEM_BYTES);

    // 1) LayerNorm + weight prep
    ln_kernel<<<NTOK, 288>>>(x, ln_g, ln_b, p_xn);
    prep_w<<<296, 256>>>(Wq, Wk, Wv, Wg, Wo);

    // 2) Four projection GEMMs (grid.z): [49152,384] @ [384,384]^T -> bf16
    {
        GemmPtrs gp;
        gp.bias[0] = bq; gp.bias[1] = bk; gp.bias[2] = bv; gp.bias[3] = bg;
        for (int zz = 0; zz < 4; zz++) {
            gp.C[zz] = p_proj + (size_t)zz * ROWS3 * D3C;
            gp.W[zz] = p_wt + (size_t)zz * (W4SZ / 2);
        }
        gp.resid = nullptr; gp.g = nullptr;
        dim3 grid(D3C / 128, ROWS3 / 256, 4);
        mma_gemm<D3C, false, true><<<grid, 256, SMEM_BYTES>>>(p_xn, gp, D3C);
    }

    // 3) Attention + gate
    attn_kernel<<<NTOK * NHEAD / 256, 256>>>();

    // 4) Output GEMM + bias + residual*g -> fp32
    {
        GemmPtrs gp;
        gp.bias[0] = bo; gp.C[0] = out; gp.W[0] = p_wt + WO_OFF / 2;
        gp.bias[1] = gp.bias[2] = gp.bias[3] = nullptr;
        gp.C[1] = gp.C[2] = gp.C[3] = nullptr;
        gp.W[1] = gp.W[2] = gp.W[3] = nullptr;
        gp.resid = x; gp.g = gsc;
        dim3 grid(DMOD / 128, NTOK / 256, 1);
        mma_gemm<DMOD, true, false><<<grid, 256, SMEM_BYTES>>>(
            reinterpret_cast<const uint32_t*>(p_hout), gp, DMOD);
    }
}

// round 11
// speedup vs baseline: 5.1215x; 1.1079x over previous
#include <cuda_runtime.h>
#include <cuda_bf16.h>
#include <cstdint>
#include <math.h>

// ---------------------------------------------------------------------------
// Problem constants
// ---------------------------------------------------------------------------
#define NTOK   16384          // B*L
#define DMOD   1152           // D
#define D3C    384            // D/3
#define NHEAD  16
#define DK3C   24
#define ROWS3  (NTOK * 3)     // 49152
#define SCORE_SCALE 0.1178511301977579f   // 1/sqrt(72)

#define W4SZ   (D3C * D3C)
#define WOSZ   (DMOD * DMOD)
#define WO_OFF (4 * W4SZ)
#define WT_WORDS ((WO_OFF + WOSZ) / 2)

// ---------------------------------------------------------------------------
// Scratch
// ---------------------------------------------------------------------------
__device__ __align__(16) uint32_t g_xn[NTOK * DMOD / 2];          // LN out, bf16x2
__device__ __align__(16) __nv_bfloat16 g_proj[4][ROWS3 * D3C];    // q,k,v,gate bf16
__device__ __align__(16) __nv_bfloat16 g_hout[NTOK * DMOD];       // attn out, bf16
__device__ __align__(16) uint32_t g_wt[WT_WORDS];                 // weights, bf16x2

// ---------------------------------------------------------------------------
// Helpers
// ---------------------------------------------------------------------------
__device__ __forceinline__ uint32_t pack_bf16x2(float lo, float hi) {
    uint32_t r;
    asm("cvt.rn.bf16x2.f32 %0, %1, %2;" : "=r"(r) : "f"(hi), "f"(lo));
    return r;
}
__device__ __forceinline__ uint32_t smem_u32(const void* p) {
    uint32_t a;
    asm("{ .reg .u64 t; cvta.to.shared.u64 t, %1; cvt.u32.u64 %0, t; }" : "=r"(a) : "l"(p));
    return a;
}
__device__ __forceinline__ void cp_async16(uint32_t dst, const void* src) {
    asm volatile("cp.async.cg.shared.global [%0], [%1], 16;" :: "r"(dst), "l"(src));
}
__device__ __forceinline__ void cp_commit() {
    asm volatile("cp.async.commit_group;" ::: "memory");
}
template<int N>
__device__ __forceinline__ void cp_wait() {
    asm volatile("cp.async.wait_group %0;" :: "n"(N) : "memory");
}
__device__ __forceinline__ void mma_bf16(float* d, const uint32_t* a, const uint32_t* b) {
    asm volatile(
        "mma.sync.aligned.m16n8k16.row.col.f32.bf16.bf16.f32 "
        "{%0,%1,%2,%3}, {%4,%5,%6,%7}, {%8,%9}, {%0,%1,%2,%3};"
        : "+f"(d[0]), "+f"(d[1]), "+f"(d[2]), "+f"(d[3])
        : "r"(a[0]), "r"(a[1]), "r"(a[2]), "r"(a[3]), "r"(b[0]), "r"(b[1]));
}
__device__ __forceinline__ void ldmatrix_x4(uint32_t* r, uint32_t addr) {
    asm volatile("ldmatrix.sync.aligned.m8n8.x4.shared.b16 {%0,%1,%2,%3}, [%4];"
        : "=r"(r[0]), "=r"(r[1]), "=r"(r[2]), "=r"(r[3]) : "r"(addr));
}
__device__ __forceinline__ void bf8_to_f(const uint4& u, float* f) {
    const __nv_bfloat162* p = reinterpret_cast<const __nv_bfloat162*>(&u);
    #pragma unroll
    for (int i = 0; i < 4; i++) {
        float2 v = __bfloat1622float2(p[i]);
        f[2 * i] = v.x; f[2 * i + 1] = v.y;
    }
}

// ---------------------------------------------------------------------------
// Kernel 1: LayerNorm -> bf16x2
// ---------------------------------------------------------------------------
__global__ void ln_kernel(const float* __restrict__ x,
                          const float* __restrict__ gamma,
                          const float* __restrict__ beta,
                          uint32_t* __restrict__ xn) {
    const int n = blockIdx.x;
    const int t = threadIdx.x;
    const float4* xr = reinterpret_cast<const float4*>(x + (size_t)n * DMOD);
    float4 v = xr[t];
    float s  = v.x + v.y + v.z + v.w;
    float ss = v.x * v.x + v.y * v.y + v.z * v.z + v.w * v.w;
    #pragma unroll
    for (int off = 16; off > 0; off >>= 1) {
        s  += __shfl_xor_sync(0xffffffffu, s,  off);
        ss += __shfl_xor_sync(0xffffffffu, ss, off);
    }
    __shared__ float red_s[9], red_ss[9], stat[2];
    const int warp = t >> 5, lane = t & 31;
    if (lane == 0) { red_s[warp] = s; red_ss[warp] = ss; }
    __syncthreads();
    if (t == 0) {
        float ts = 0.f, tss = 0.f;
        #pragma unroll
        for (int i = 0; i < 9; i++) { ts += red_s[i]; tss += red_ss[i]; }
        float mu  = ts * (1.0f / DMOD);
        float var = tss * (1.0f / DMOD) - mu * mu;
        stat[0] = mu; stat[1] = rsqrtf(var + 1e-6f);
    }
    __syncthreads();
    const float mu = stat[0], rstd = stat[1];
    const float4 gm = reinterpret_cast<const float4*>(gamma)[t];
    const float4 be = reinterpret_cast<const float4*>(beta)[t];
    uint2 o;
    o.x = pack_bf16x2((v.x - mu) * rstd * gm.x + be.x, (v.y - mu) * rstd * gm.y + be.y);
    o.y = pack_bf16x2((v.z - mu) * rstd * gm.z + be.z, (v.w - mu) * rstd * gm.w + be.w);
    reinterpret_cast<uint2*>(xn + (size_t)n * (DMOD / 2))[t] = o;
}

// ---------------------------------------------------------------------------
// Kernel 1b: weights fp32 -> bf16x2
// ---------------------------------------------------------------------------
__global__ void prep_w(const float* __restrict__ Wq, const float* __restrict__ Wk,
                       const float* __restrict__ Wv, const float* __restrict__ Wg,
                       const float* __restrict__ Wo) {
    for (int i = blockIdx.x * blockDim.x + threadIdx.x; i < WT_WORDS;
         i += gridDim.x * blockDim.x) {
        float lo, hi;
        if (i < WO_OFF / 2) {
            const int z = i / (W4SZ / 2), r = i % (W4SZ / 2);
            const float* W = (z == 0) ? Wq : (z == 1) ? Wk : (z == 2) ? Wv : Wg;
            lo = W[2 * r]; hi = W[2 * r + 1];
        } else {
            const int j = i - WO_OFF / 2;
            lo = Wo[2 * j]; hi = Wo[2 * j + 1];
        }
        g_wt[i] = pack_bf16x2(lo, hi);
    }
}

// ---------------------------------------------------------------------------
// bf16 mma.sync GEMM with ldmatrix.  Block 256x128, 8 warps, warp 64x64.
// K-chunk = 64 (32 u32 words per row), 3-stage cp.async pipeline,
// ONE barrier per 64-K.  Same loop invariants as the validated 32-K version.
// ---------------------------------------------------------------------------
struct GemmPtrs {
    const float*    bias[4];
    void*           C[4];
    const uint32_t* W[4];
    const float*    resid;
    const float*    g;
};

#define PITCH  36                 // u32 words per smem row (32 data + 4 pad)
#define LROWS  384                // 256 A rows + 128 B rows per stage
#define SSW    (LROWS * PITCH)    // u32 words per stage (13824)
#define NSTG   3

template<int KD, bool RES, bool OUTB>
__global__ __launch_bounds__(256)
void mma_gemm(const uint32_t* __restrict__ A, GemmPtrs gp, int Ntot) {
    constexpr int KW = KD / 2;          // u32 words per gmem row
    constexpr int NC = KD / 64;         // 64-deep K chunks (6 or 18)
    extern __shared__ uint32_t sm[];

    const int tid  = threadIdx.x;
    const int wid  = tid >> 5;
    const int lane = tid & 31;
    const int g    = lane >> 2;
    const int t4   = lane & 3;
    const int wm0  = (wid >> 1) * 64;
    const int wn0  = (wid & 1) * 64;
    const int z    = blockIdx.z;

    const uint32_t* W    = gp.W[z];
    const float*    bias = gp.bias[z];
    const int bm = blockIdx.y * 256;
    const int bn = blockIdx.x * 128;

    const uint32_t smaddr = smem_u32(sm);

    // ldmatrix byte offsets within a stage (16-K half u adds u*32 bytes).
    uint32_t adrA[4];
    #pragma unroll
    for (int ms = 0; ms < 4; ms++) {
        const int row = wm0 + ms * 16 + (lane & 15);
        const int wof = ((lane >> 4) & 1) * 4;
        adrA[ms] = (uint32_t)(row * PITCH + wof) * 4u;
    }
    uint32_t adrB[4];
    #pragma unroll
    for (int ps = 0; ps < 4; ps++) {
        const int row = wn0 + ps * 16 + (lane & 7) + ((lane >> 4) & 1) * 8;
        const int wof = ((lane >> 3) & 1) * 4;
        adrB[ps] = (uint32_t)(256 * PITCH + row * PITCH + wof) * 4u;
    }

    // Load one 64-K chunk: 384 rows x 32 words; 12 cp.async16 per thread.
    auto load_stage = [&](int c, int slot) {
        const int k0 = c * 32;                 // u32 word offset in gmem row
        const uint32_t sb = smaddr + (uint32_t)(slot * SSW) * 4u;
        #pragma unroll
        for (int t = 0; t < 12; t++) {
            const int idx = tid + t * 256;     // 0..3071
            const int row = idx >> 3;          // 0..383
            const int q   = idx & 7;           // 16B eighth within the row
            const uint32_t* src = (row < 256)
                ? (A + (size_t)(bm + row) * KW + k0 + q * 4)
                : (W + (size_t)(bn + row - 256) * KW + k0 + q * 4);
            cp_async16(sb + (uint32_t)(row * PITCH + q * 4) * 4u, src);
        }
        cp_commit();
    };

    float acc[4][8][4];
    #pragma unroll
    for (int i = 0; i < 4; i++)
        #pragma unroll
        for (int j = 0; j < 8; j++)
            #pragma unroll
            for (int r = 0; r < 4; r++) acc[i][j][r] = 0.f;

    load_stage(0, 0);
    load_stage(1, 1);

    int cslot = 0;   // slot of chunk c
    int lslot = 2;   // slot for chunk c+2
    for (int c = 0; c < NC; c++) {
        if (c < NC - 1) cp_wait<1>(); else cp_wait<0>();
        __syncthreads();
        if (c + 2 < NC) {
            load_stage(c + 2, lslot);
            if (++lslot == NSTG) lslot = 0;
        }

        const uint32_t sbase = smaddr + (uint32_t)(cslot * SSW) * 4u;
        if (++cslot == NSTG) cslot = 0;

        #pragma unroll
        for (int u = 0; u < 4; u++) {          // four 16-K halves of the chunk
            const uint32_t hbase = sbase + u * 32u;
            uint32_t afr[4][4];
            #pragma unroll
            for (int ms = 0; ms < 4; ms++)
                ldmatrix_x4(afr[ms], hbase + adrA[ms]);
            #pragma unroll
            for (int ps = 0; ps < 4; ps++) {
                uint32_t bfr[4];
                ldmatrix_x4(bfr, hbase + adrB[ps]);
                #pragma unroll
                for (int ms = 0; ms < 4; ms++) {
                    mma_bf16(acc[ms][2 * ps],     afr[ms], bfr);
                    mma_bf16(acc[ms][2 * ps + 1], afr[ms], bfr + 2);
                }
            }
        }
    }

    // Epilogue
    const float gval = RES ? __ldg(gp.g) : 0.f;
    #pragma unroll
    for (int ms = 0; ms < 4; ms++) {
        const int row0 = bm + wm0 + ms * 16 + g;
        #pragma unroll
        for (int ns = 0; ns < 8; ns++) {
            const int col = bn + wn0 + ns * 8 + 2 * t4;
            const float b0 = __ldg(bias + col);
            const float b1 = __ldg(bias + col + 1);
            float o0 = acc[ms][ns][0] + b0;
            float o1 = acc[ms][ns][1] + b1;
            float o2 = acc[ms][ns][2] + b0;
            float o3 = acc[ms][ns][3] + b1;
            if (RES) {
                const float* r0 = gp.resid + (size_t)row0 * Ntot + col;
                const float* r1 = gp.resid + (size_t)(row0 + 8) * Ntot + col;
                o0 = fmaf(r0[0], gval, o0);
                o1 = fmaf(r0[1], gval, o1);
                o2 = fmaf(r1[0], gval, o2);
                o3 = fmaf(r1[1], gval, o3);
            }
            if (OUTB) {
                uint32_t* Cw = (uint32_t*)gp.C[z];
                Cw[(size_t)row0 * (Ntot / 2) + (col >> 1)]       = pack_bf16x2(o0, o1);
                Cw[(size_t)(row0 + 8) * (Ntot / 2) + (col >> 1)] = pack_bf16x2(o2, o3);
            } else {
                float* C = (float*)gp.C[z];
                *reinterpret_cast<float2*>(C + (size_t)row0 * Ntot + col)       = make_float2(o0, o1);
                *reinterpret_cast<float2*>(C + (size_t)(row0 + 8) * Ntot + col) = make_float2(o2, o3);
            }
        }
    }
}

// ---------------------------------------------------------------------------
// Attention + gate: one thread per (token, head).
// launch_bounds(256,4) caps regs at 64 -> 4 blocks/SM for more MLP.
// ---------------------------------------------------------------------------
__global__ __launch_bounds__(256, 4)
void attn_kernel() {
    const int t = blockIdx.x * blockDim.x + threadIdx.x;
    const int n = t >> 4;
    const int h = t & 15;
    const size_t ebase = (size_t)n * 3 * D3C + h * DK3C;

    const uint4* q4 = reinterpret_cast<const uint4*>(&g_proj[0][ebase]);
    const uint4* k4 = reinterpret_cast<const uint4*>(&g_proj[1][ebase]);
    const uint4* v4 = reinterpret_cast<const uint4*>(&g_proj[2][ebase]);
    const uint4* g4 = reinterpret_cast<const uint4*>(&g_proj[3][ebase]);

    float s[3][3] = {{0.f,0.f,0.f},{0.f,0.f,0.f},{0.f,0.f,0.f}};
    #pragma unroll
    for (int c = 0; c < 3; c++) {
        float qf[3][8], kf[3][8];
        #pragma unroll
        for (int i = 0; i < 3; i++) {
            bf8_to_f(q4[i * 48 + c], qf[i]);
            bf8_to_f(k4[i * 48 + c], kf[i]);
        }
        #pragma unroll
        for (int i = 0; i < 3; i++)
            #pragma unroll
            for (int j = 0; j < 3; j++) {
                float p = 0.f;
                #pragma unroll
                for (int d = 0; d < 8; d++) p = fmaf(qf[i][d], kf[j][d], p);
                s[i][j] += p;
            }
    }

    float a[3][3];
    #pragma unroll
    for (int i = 0; i < 3; i++) {
        float s0 = s[i][0] * SCORE_SCALE, s1 = s[i][1] * SCORE_SCALE, s2 = s[i][2] * SCORE_SCALE;
        float m = fmaxf(s0, fmaxf(s1, s2));
        float e0 = expf(s0 - m), e1 = expf(s1 - m), e2 = expf(s2 - m);
        float inv = 1.0f / (e0 + e1 + e2);
        a[i][0] = e0 * inv; a[i][1] = e1 * inv; a[i][2] = e2 * inv;
    }

    const size_t obase = (size_t)n * DMOD + h * DK3C;
    #pragma unroll
    for (int c = 0; c < 3; c++) {
        float vf[3][8], gf[3][8];
        #pragma unroll
        for (int j = 0; j < 3; j++) bf8_to_f(v4[j * 48 + c], vf[j]);
        #pragma unroll
        for (int i = 0; i < 3; i++) bf8_to_f(g4[i * 48 + c], gf[i]);
        #pragma unroll
        for (int i = 0; i < 3; i++) {
            uint4 ou;
            uint32_t* ow = reinterpret_cast<uint32_t*>(&ou);
            #pragma unroll
            for (int p = 0; p < 4; p++) {
                float o0 = a[i][0] * vf[0][2*p]   + a[i][1] * vf[1][2*p]   + a[i][2] * vf[2][2*p];
                float o1 = a[i][0] * vf[0][2*p+1] + a[i][1] * vf[1][2*p+1] + a[i][2] * vf[2][2*p+1];
                o0 *= 1.0f / (1.0f + expf(-gf[i][2*p]));
                o1 *= 1.0f / (1.0f + expf(-gf[i][2*p+1]));
                ow[p] = pack_bf16x2(o0, o1);
            }
            *reinterpret_cast<uint4*>(&g_hout[obase + (size_t)i * D3C + c * 8]) = ou;
        }
    }
}

// ---------------------------------------------------------------------------
// Launch
// ---------------------------------------------------------------------------
extern "C" void kernel_launch(void* const* d_in, const int* in_sizes, int n_in,
                              void* d_out, int out_size) {
    const float* x    = (const float*)d_in[0];
    const float* ln_g = (const float*)d_in[1];
    const float* ln_b = (const float*)d_in[2];
    const float* Wq   = (const float*)d_in[3];
    const float* bq   = (const float*)d_in[4];
    const float* Wk   = (const float*)d_in[5];
    const float* bk   = (const float*)d_in[6];
    const float* Wv   = (const float*)d_in[7];
    const float* bv   = (const float*)d_in[8];
    const float* Wg   = (const float*)d_in[9];
    const float* bg   = (const float*)d_in[10];
    const float* Wo   = (const float*)d_in[11];
    const float* bo   = (const float*)d_in[12];
    const float* gsc  = (const float*)d_in[13];
    float* out = (float*)d_out;

    uint32_t *p_xn, *p_wt;
    __nv_bfloat16 *p_proj, *p_hout;
    cudaGetSymbolAddress((void**)&p_xn,   g_xn);
    cudaGetSymbolAddress((void**)&p_proj, g_proj);
    cudaGetSymbolAddress((void**)&p_hout, g_hout);
    cudaGetSymbolAddress((void**)&p_wt,   g_wt);

    const int SMEM_BYTES = NSTG * SSW * 4;   // 3 * 13824 * 4 = 165888
    cudaFuncSetAttribute((const void*)mma_gemm<D3C, false, true>,
                         cudaFuncAttributeMaxDynamicSharedMemorySize, SMEM_BYTES);
    cudaFuncSetAttribute((const void*)mma_gemm<DMOD, true, false>,
                         cudaFuncAttributeMaxDynamicSharedMemorySize, SMEM_BYTES);

    // 1) LayerNorm + weight prep
    ln_kernel<<<NTOK, 288>>>(x, ln_g, ln_b, p_xn);
    prep_w<<<296, 256>>>(Wq, Wk, Wv, Wg, Wo);

    // 2) Four projection GEMMs (grid.z): [49152,384] @ [384,384]^T -> bf16
    {
        GemmPtrs gp;
        gp.bias[0] = bq; gp.bias[1] = bk; gp.bias[2] = bv; gp.bias[3] = bg;
        for (int zz = 0; zz < 4; zz++) {
            gp.C[zz] = p_proj + (size_t)zz * ROWS3 * D3C;
            gp.W[zz] = p_wt + (size_t)zz * (W4SZ / 2);
        }
        gp.resid = nullptr; gp.g = nullptr;
        dim3 grid(D3C / 128, ROWS3 / 256, 4);
        mma_gemm<D3C, false, true><<<grid, 256, SMEM_BYTES>>>(p_xn, gp, D3C);
    }

    // 3) Attention + gate
    attn_kernel<<<NTOK * NHEAD / 256, 256>>>();

    // 4) Output GEMM + bias + residual*g -> fp32
    {
        GemmPtrs gp;
        gp.bias[0] = bo; gp.C[0] = out; gp.W[0] = p_wt + WO_OFF / 2;
        gp.bias[1] = gp.bias[2] = gp.bias[3] = nullptr;
        gp.C[1] = gp.C[2] = gp.C[3] = nullptr;
        gp.W[1] = gp.W[2] = gp.W[3] = nullptr;
        gp.resid = x; gp.g = gsc;
        dim3 grid(DMOD / 128, NTOK / 256, 1);
        mma_gemm<DMOD, true, false><<<grid, 256, SMEM_BYTES>>>(
            reinterpret_cast<const uint32_t*>(p_hout), gp, DMOD);
    }
}